// round 1
// baseline (speedup 1.0000x reference)
#include <cuda_runtime.h>
#include <math.h>

#define THREADS 256

// ---------------- scratch (__device__ globals; allocation-free per rules) ----------------
__device__ float g_spd[33554432];     // (8,256,128,128)  space-to-depth of x
__device__ float g_w0[75497472];      // (8,576,128,128)  silu(bn(conv_gw))
__device__ float g_pool[75497472];    // (8,576,128,128)  2x2 avg, 127x127 valid, zero pad row/col 127
__device__ float g_X1[37748736];      // (8,288,128,128)  row rfft: per row [re v0..63 | im v0..63]
__device__ float g_cat[37748736];     // (8,1152,64,64)   [lowRe lowIm highRe highIm]
__device__ float g_mp[9437184];       // (8,288,64,64)    maxpool(x2)
__device__ float g_weight[18874368];  // (8,576,64,64)    concat(x1_fm, x2_cv2)
__device__ float g_f[18874368];       // (8,576,64,64)    relu(bn2(silu(bn1(conv_gf))))
__device__ float g_wd[18874368];      // (8,576,64,64)    f * softmax(weight)
__device__ float g_col[75497472];     // (8,2304,64,64)   im2col for conv_gf
__device__ float g_tw[16384];         // (128 q, [cos 0..63 | -sin 0..63])
__device__ float g_ct[128];
__device__ float g_st[128];

// ---------------- init: DFT twiddles ----------------
__global__ void init_tw_kernel() {
    int i = blockIdx.x * blockDim.x + threadIdx.x;
    const double TWO_PI = 6.283185307179586476925286766559;
    if (i < 16384) {
        int q = i >> 7, v = i & 127;
        if (v < 64)
            g_tw[i] = (float)cos(TWO_PI * (double)((q * v) & 127) / 128.0);
        else
            g_tw[i] = (float)(-sin(TWO_PI * (double)((q * (v - 64)) & 127) / 128.0));
    }
    if (i < 128) {
        g_ct[i] = (float)cos(TWO_PI * (double)i / 128.0);
        g_st[i] = (float)sin(TWO_PI * (double)i / 128.0);
    }
}

// ---------------- space-to-depth ----------------
__global__ void spd_kernel(const float* __restrict__ x) {
    int i = blockIdx.x * THREADS + threadIdx.x;
    if (i >= 33554432) return;
    int q = i & 127, p = (i >> 7) & 127, s = (i >> 14) & 255, b = i >> 22;
    int quad = s >> 6, c = s & 63;
    int r  = 2 * p + (quad & 1);
    int cc = 2 * q + (quad >> 1);
    g_spd[i] = x[((size_t)(b * 64 + c) * 256 + r) * 256 + cc];
}

// ---------------- 2x2 stride-1 average; zero pad to 128x128 ----------------
__global__ void avgpool_kernel() {
    int i = blockIdx.x * THREADS + threadIdx.x;
    if (i >= 75497472) return;
    int q = i & 127, p = (i >> 7) & 127;
    int cb = i >> 14;
    const float* s = g_w0 + (size_t)cb * 16384;
    float v = 0.f;
    if (p < 127 && q < 127) {
        int o = (p << 7) + q;
        v = 0.25f * (s[o] + s[o + 128] + s[o + 1] + s[o + 129]);
    }
    g_pool[i] = v;
}

// ---------------- 3x3 stride-2 maxpool (pad 1, valid 127x127) on x2 ----------------
__global__ void maxpool_kernel() {
    int i = blockIdx.x * THREADS + threadIdx.x;
    if (i >= 9437184) return;
    int v = i & 63, u = (i >> 6) & 63;
    int cb = i >> 12;
    int c = cb % 288, b = cb / 288;
    const float* s = g_pool + (size_t)(b * 576 + 288 + c) * 16384;
    int r0 = max(2 * u - 1, 0), r1 = min(2 * u + 1, 126);
    int c0 = max(2 * v - 1, 0), c1 = min(2 * v + 1, 126);
    float m = -3.4e38f;
    for (int r = r0; r <= r1; r++)
        for (int cc = c0; cc <= c1; cc++)
            m = fmaxf(m, s[(r << 7) + cc]);
    g_mp[i] = m;
}

// ---------------- im2col for conv_gf (3x3, stride 2, pad 1) ----------------
__global__ void im2col_kernel() {
    int i = blockIdx.x * THREADS + threadIdx.x;
    if (i >= 75497472) return;
    int n = i & 4095;
    int v = n & 63, u = n >> 6;
    int kb = i >> 12;
    int k = kb % 2304, b = kb / 2304;
    int ic = k / 9, t = k - ic * 9;
    int di = t / 3, dj = t - di * 3;
    int r  = 2 * u + di - 1;
    int cc = 2 * v + dj - 1;
    float val = 0.f;
    if ((unsigned)r < 128u && (unsigned)cc < 128u)
        val = g_spd[((size_t)(b * 256 + ic) << 14) + (r << 7) + cc];
    g_col[i] = val;
}

// ---------------- column FFT (128-pt complex) -> cat layout ----------------
__global__ __launch_bounds__(256) void fft_col_kernel() {
    __shared__ float Xre[128][32];
    __shared__ float Xim[128][32];
    __shared__ float cs[128], sn[128];
    int blk = blockIdx.x;               // b*288 + c
    int b = blk / 288, c = blk % 288;
    int tid = threadIdx.x;
    if (tid < 128) { cs[tid] = g_ct[tid]; sn[tid] = g_st[tid]; }
    const float* X1 = g_X1 + (size_t)(b * 288 + c) * 16384;
    size_t cbase = (size_t)b * 1152 * 4096;
    for (int half = 0; half < 2; half++) {
        int v0 = half << 5;
        __syncthreads();
        for (int e = tid; e < 4096; e += 256) {
            int p = e >> 5, v = e & 31;
            Xre[p][v] = X1[(p << 7) + v0 + v];
            Xim[p][v] = X1[(p << 7) + 64 + v0 + v];
        }
        __syncthreads();
        for (int r = 0; r < 16; r++) {
            int o = (r << 8) + tid;     // 0..4095
            int u = o >> 5, v = o & 31;
            float re = 0.f, im = 0.f;
            #pragma unroll 8
            for (int p = 0; p < 128; p++) {
                int idx = (u * p) & 127;
                float cc = cs[idx], ss = sn[idx];
                float xr = Xre[p][v], xi = Xim[p][v];
                re = fmaf(xr, cc, re); re = fmaf(xi, ss, re);
                im = fmaf(xi, cc, im); im = fmaf(-xr, ss, im);
            }
            int vv = v0 + v;
            int ur = u & 63;
            int choff = (u < 64) ? c : (576 + c);
            g_cat[cbase + (size_t)choff * 4096 + (ur << 6) + vv] = re;
            g_cat[cbase + (size_t)(choff + 288) * 4096 + (ur << 6) + vv] = im;
        }
    }
}

// ---------------- softmax over t (9) and gate with f ----------------
__global__ void softmax_wd_kernel() {
    int i = blockIdx.x * THREADS + threadIdx.x;
    if (i >= 2097152) return;
    int n = i & 4095;
    int cb = i >> 12;
    int c = cb & 63, b = cb >> 6;
    size_t base = (size_t)(b * 576 + c * 9) * 4096 + n;
    float w[9];
    float mx = -3.4e38f;
    #pragma unroll
    for (int t = 0; t < 9; t++) { w[t] = g_weight[base + t * 4096]; mx = fmaxf(mx, w[t]); }
    float sum = 0.f;
    #pragma unroll
    for (int t = 0; t < 9; t++) { w[t] = expf(w[t] - mx); sum += w[t]; }
    float inv = 1.f / sum;
    #pragma unroll
    for (int t = 0; t < 9; t++)
        g_wd[base + t * 4096] = g_f[base + t * 4096] * w[t] * inv;
}

// ---------------- generic fp32 GEMM: C(MxN) = A(MxK,row) @ B(KxN,row) + epilogue ----------------
// mode 0: none; mode 1: silu(v*g1+b1); mode 2: relu(silu(v*g1+b1)*g2+b2)
// Requirements: K % 16 == 0, N % 128 == 0. M arbitrary (guarded).
__global__ __launch_bounds__(256) void sgemm_kernel(
    const float* __restrict__ A, const float* __restrict__ B, float* __restrict__ C,
    int M, int N, int K,
    long long sA, long long sB, long long sC,
    const float* __restrict__ G1, const float* __restrict__ Bi1,
    const float* __restrict__ G2, const float* __restrict__ Bi2, int mode)
{
    __shared__ float As[16][128];
    __shared__ float Bs[16][128];
    int tid = threadIdx.x;
    int bn0 = blockIdx.x << 7, bm0 = blockIdx.y << 7;
    A += (long long)blockIdx.z * sA;
    B += (long long)blockIdx.z * sB;
    C += (long long)blockIdx.z * sC;

    int aRow = tid >> 1;
    int aK   = (tid & 1) << 3;
    int bRow = tid >> 5;
    int bCol = (tid & 31) << 2;
    int ty = tid >> 4, tx = tid & 15;

    float acc[8][8];
    #pragma unroll
    for (int i = 0; i < 8; i++)
        #pragma unroll
        for (int j = 0; j < 8; j++) acc[i][j] = 0.f;

    int mA = bm0 + aRow;
    bool aOk = (mA < M);
    const float* Ap = A + (long long)(aOk ? mA : 0) * K + aK;
    const float* Bp = B + (long long)bRow * N + bn0 + bCol;

    for (int k0 = 0; k0 < K; k0 += 16) {
        float4 a0, a1;
        if (aOk) {
            a0 = *(const float4*)(Ap + k0);
            a1 = *(const float4*)(Ap + k0 + 4);
        } else {
            a0 = make_float4(0.f, 0.f, 0.f, 0.f);
            a1 = a0;
        }
        float4 b0 = *(const float4*)(Bp + (long long)k0 * N);
        float4 b1 = *(const float4*)(Bp + (long long)(k0 + 8) * N);
        As[aK + 0][aRow] = a0.x; As[aK + 1][aRow] = a0.y;
        As[aK + 2][aRow] = a0.z; As[aK + 3][aRow] = a0.w;
        As[aK + 4][aRow] = a1.x; As[aK + 5][aRow] = a1.y;
        As[aK + 6][aRow] = a1.z; As[aK + 7][aRow] = a1.w;
        *(float4*)&Bs[bRow][bCol]     = b0;
        *(float4*)&Bs[bRow + 8][bCol] = b1;
        __syncthreads();
        #pragma unroll
        for (int k = 0; k < 16; k++) {
            float4 av0 = *(const float4*)&As[k][ty << 3];
            float4 av1 = *(const float4*)&As[k][(ty << 3) + 4];
            float4 bv0 = *(const float4*)&Bs[k][tx << 3];
            float4 bv1 = *(const float4*)&Bs[k][(tx << 3) + 4];
            float av[8] = {av0.x, av0.y, av0.z, av0.w, av1.x, av1.y, av1.z, av1.w};
            float bv[8] = {bv0.x, bv0.y, bv0.z, bv0.w, bv1.x, bv1.y, bv1.z, bv1.w};
            #pragma unroll
            for (int i = 0; i < 8; i++)
                #pragma unroll
                for (int j = 0; j < 8; j++)
                    acc[i][j] = fmaf(av[i], bv[j], acc[i][j]);
        }
        __syncthreads();
    }

    int n0 = bn0 + (tx << 3);
    #pragma unroll
    for (int i = 0; i < 8; i++) {
        int m = bm0 + (ty << 3) + i;
        if (m >= M) break;
        float g1v = 0.f, b1v = 0.f, g2v = 0.f, b2v = 0.f;
        if (mode >= 1) { g1v = G1[m]; b1v = Bi1[m]; }
        if (mode == 2) { g2v = G2[m]; b2v = Bi2[m]; }
        float o[8];
        #pragma unroll
        for (int j = 0; j < 8; j++) {
            float v = acc[i][j];
            if (mode >= 1) {
                float t = v * g1v + b1v;
                v = t / (1.f + expf(-t));
                if (mode == 2) {
                    float u2 = v * g2v + b2v;
                    v = u2 > 0.f ? u2 : 0.f;
                }
            }
            o[j] = v;
        }
        float4* Cp = (float4*)&C[(long long)m * N + n0];
        Cp[0] = make_float4(o[0], o[1], o[2], o[3]);
        Cp[1] = make_float4(o[4], o[5], o[6], o[7]);
    }
}

// ---------------- host ----------------
extern "C" void kernel_launch(void* const* d_in, const int* in_sizes, int n_in,
                              void* d_out, int out_size) {
    const float* x     = (const float*)d_in[0];
    const float* w_gw  = (const float*)d_in[1];
    const float* gg    = (const float*)d_in[2];
    const float* bg    = (const float*)d_in[3];
    const float* w_fm  = (const float*)d_in[4];
    const float* gfm   = (const float*)d_in[5];
    const float* bfm   = (const float*)d_in[6];
    const float* w_cv2 = (const float*)d_in[7];
    const float* gcv   = (const float*)d_in[8];
    const float* bcv   = (const float*)d_in[9];
    const float* w_gf  = (const float*)d_in[10];
    const float* ggf   = (const float*)d_in[11];
    const float* bgf   = (const float*)d_in[12];
    const float* ggf2  = (const float*)d_in[13];
    const float* bgf2  = (const float*)d_in[14];
    const float* w_out = (const float*)d_in[15];
    float* out = (float*)d_out;

    float *p_spd, *p_w0, *p_pool, *p_X1, *p_cat, *p_mp, *p_weight, *p_f, *p_wd, *p_col, *p_tw;
    cudaGetSymbolAddress((void**)&p_spd,    g_spd);
    cudaGetSymbolAddress((void**)&p_w0,     g_w0);
    cudaGetSymbolAddress((void**)&p_pool,   g_pool);
    cudaGetSymbolAddress((void**)&p_X1,     g_X1);
    cudaGetSymbolAddress((void**)&p_cat,    g_cat);
    cudaGetSymbolAddress((void**)&p_mp,     g_mp);
    cudaGetSymbolAddress((void**)&p_weight, g_weight);
    cudaGetSymbolAddress((void**)&p_f,      g_f);
    cudaGetSymbolAddress((void**)&p_wd,     g_wd);
    cudaGetSymbolAddress((void**)&p_col,    g_col);
    cudaGetSymbolAddress((void**)&p_tw,     g_tw);

    init_tw_kernel<<<64, 256>>>();
    spd_kernel<<<131072, 256>>>(x);

    // conv_gw: per-batch (576x256) @ (256x16384), silu(bn)
    {
        dim3 g(128, 5, 8);
        sgemm_kernel<<<g, 256>>>(w_gw, p_spd, p_w0, 576, 16384, 256,
                                 0LL, 256LL * 16384, 576LL * 16384,
                                 gg, bg, nullptr, nullptr, 1);
    }
    avgpool_kernel<<<294912, 256>>>();

    // row rfft as GEMM: per-batch (36864x128) @ (128x128 twiddle)
    {
        dim3 g(1, 288, 8);
        sgemm_kernel<<<g, 256>>>(p_pool, p_tw, p_X1, 36864, 128, 128,
                                 576LL * 16384, 0LL, 288LL * 16384,
                                 nullptr, nullptr, nullptr, nullptr, 0);
    }
    fft_col_kernel<<<2304, 256>>>();

    // conv_fm: per-batch (288x1152) @ (1152x4096) -> weight[:,0:288]
    {
        dim3 g(32, 3, 8);
        sgemm_kernel<<<g, 256>>>(w_fm, p_cat, p_weight, 288, 4096, 1152,
                                 0LL, 1152LL * 4096, 576LL * 4096,
                                 gfm, bfm, nullptr, nullptr, 1);
    }
    maxpool_kernel<<<36864, 256>>>();

    // conv_cv2: per-batch (288x288) @ (288x4096) -> weight[:,288:576]
    {
        dim3 g(32, 3, 8);
        sgemm_kernel<<<g, 256>>>(w_cv2, p_mp, p_weight + 288 * 4096, 288, 4096, 288,
                                 0LL, 288LL * 4096, 576LL * 4096,
                                 gcv, bcv, nullptr, nullptr, 1);
    }
    im2col_kernel<<<294912, 256>>>();

    // conv_gf: per-batch (576x2304) @ (2304x4096), relu(bn2(silu(bn1)))
    {
        dim3 g(32, 5, 8);
        sgemm_kernel<<<g, 256>>>(w_gf, p_col, p_f, 576, 4096, 2304,
                                 0LL, 2304LL * 4096, 576LL * 4096,
                                 ggf, bgf, ggf2, bgf2, 2);
    }
    softmax_wd_kernel<<<8192, 256>>>();

    // final (pixel-shuffle + stride-3 conv collapsed): (128x576) @ (576x4096)
    {
        dim3 g(32, 1, 8);
        sgemm_kernel<<<g, 256>>>(w_out, p_wd, out, 128, 4096, 576,
                                 0LL, 576LL * 4096, 128LL * 4096,
                                 nullptr, nullptr, nullptr, nullptr, 0);
    }
}

// round 2
// speedup vs baseline: 1.0006x; 1.0006x over previous
#include <cuda_runtime.h>
#include <math.h>

#define THREADS 256

// ---------------- scratch (__device__ globals; allocation-free per rules) ----------------
__device__ float g_spd[33554432];     // (8,256,128,128)  space-to-depth of x
__device__ float g_w0[75497472];      // (8,576,128,128)  silu(bn(conv_gw))
__device__ float g_pool[75497472];    // (8,576,128,128)  2x2 avg, 127x127 valid, zero pad row/col 127
__device__ float g_X1[37748736];      // (8,288,128,128)  row rfft: per row [re v0..63 | im v0..63]
__device__ float g_cat[37748736];     // (8,1152,64,64)   [lowRe lowIm highRe highIm]
__device__ float g_mp[9437184];       // (8,288,64,64)    maxpool(x2)
__device__ float g_weight[18874368];  // (8,576,64,64)    concat(x1_fm, x2_cv2)
__device__ float g_f[18874368];       // (8,576,64,64)    relu(bn2(silu(bn1(conv_gf))))
__device__ float g_wd[18874368];      // (8,576,64,64)    f * softmax(weight)
__device__ float g_col[75497472];     // (8,2304,64,64)   im2col for conv_gf
__device__ float g_tw[16384];         // (128 q, [cos 0..63 | -sin 0..63])
__device__ float g_ct[128];
__device__ float g_st[128];

// ---------------- init: DFT twiddles ----------------
__global__ void init_tw_kernel() {
    int i = blockIdx.x * blockDim.x + threadIdx.x;
    const double TWO_PI = 6.283185307179586476925286766559;
    if (i < 16384) {
        int q = i >> 7, v = i & 127;
        if (v < 64)
            g_tw[i] = (float)cos(TWO_PI * (double)((q * v) & 127) / 128.0);
        else
            g_tw[i] = (float)(-sin(TWO_PI * (double)((q * (v - 64)) & 127) / 128.0));
    }
    if (i < 128) {
        g_ct[i] = (float)cos(TWO_PI * (double)i / 128.0);
        g_st[i] = (float)sin(TWO_PI * (double)i / 128.0);
    }
}

// ---------------- space-to-depth ----------------
__global__ void spd_kernel(const float* __restrict__ x) {
    int i = blockIdx.x * THREADS + threadIdx.x;
    if (i >= 33554432) return;
    int q = i & 127, p = (i >> 7) & 127, s = (i >> 14) & 255, b = i >> 22;
    int quad = s >> 6, c = s & 63;
    int r  = 2 * p + (quad & 1);
    int cc = 2 * q + (quad >> 1);
    g_spd[i] = x[((size_t)(b * 64 + c) * 256 + r) * 256 + cc];
}

// ---------------- 2x2 stride-1 average; zero pad to 128x128 ----------------
__global__ void avgpool_kernel() {
    int i = blockIdx.x * THREADS + threadIdx.x;
    if (i >= 75497472) return;
    int q = i & 127, p = (i >> 7) & 127;
    int cb = i >> 14;
    const float* s = g_w0 + (size_t)cb * 16384;
    float v = 0.f;
    if (p < 127 && q < 127) {
        int o = (p << 7) + q;
        v = 0.25f * (s[o] + s[o + 128] + s[o + 1] + s[o + 129]);
    }
    g_pool[i] = v;
}

// ---------------- 3x3 stride-2 maxpool (pad 1, valid 127x127) on x2 ----------------
__global__ void maxpool_kernel() {
    int i = blockIdx.x * THREADS + threadIdx.x;
    if (i >= 9437184) return;
    int v = i & 63, u = (i >> 6) & 63;
    int cb = i >> 12;
    int c = cb % 288, b = cb / 288;
    const float* s = g_pool + (size_t)(b * 576 + 288 + c) * 16384;
    int r0 = max(2 * u - 1, 0), r1 = min(2 * u + 1, 126);
    int c0 = max(2 * v - 1, 0), c1 = min(2 * v + 1, 126);
    float m = -3.4e38f;
    for (int r = r0; r <= r1; r++)
        for (int cc = c0; cc <= c1; cc++)
            m = fmaxf(m, s[(r << 7) + cc]);
    g_mp[i] = m;
}

// ---------------- im2col for conv_gf (3x3, stride 2, pad 1) ----------------
__global__ void im2col_kernel() {
    int i = blockIdx.x * THREADS + threadIdx.x;
    if (i >= 75497472) return;
    int n = i & 4095;
    int v = n & 63, u = n >> 6;
    int kb = i >> 12;
    int k = kb % 2304, b = kb / 2304;
    int ic = k / 9, t = k - ic * 9;
    int di = t / 3, dj = t - di * 3;
    int r  = 2 * u + di - 1;
    int cc = 2 * v + dj - 1;
    float val = 0.f;
    if ((unsigned)r < 128u && (unsigned)cc < 128u)
        val = g_spd[((size_t)(b * 256 + ic) << 14) + (r << 7) + cc];
    g_col[i] = val;
}

// ---------------- column FFT (128-pt complex) -> cat layout ----------------
__global__ __launch_bounds__(256) void fft_col_kernel() {
    __shared__ float Xre[128][32];
    __shared__ float Xim[128][32];
    __shared__ float cs[128], sn[128];
    int blk = blockIdx.x;               // b*288 + c
    int b = blk / 288, c = blk % 288;
    int tid = threadIdx.x;
    if (tid < 128) { cs[tid] = g_ct[tid]; sn[tid] = g_st[tid]; }
    const float* X1 = g_X1 + (size_t)(b * 288 + c) * 16384;
    size_t cbase = (size_t)b * 1152 * 4096;
    for (int half = 0; half < 2; half++) {
        int v0 = half << 5;
        __syncthreads();
        for (int e = tid; e < 4096; e += 256) {
            int p = e >> 5, v = e & 31;
            Xre[p][v] = X1[(p << 7) + v0 + v];
            Xim[p][v] = X1[(p << 7) + 64 + v0 + v];
        }
        __syncthreads();
        for (int r = 0; r < 16; r++) {
            int o = (r << 8) + tid;     // 0..4095
            int u = o >> 5, v = o & 31;
            float re = 0.f, im = 0.f;
            #pragma unroll 8
            for (int p = 0; p < 128; p++) {
                int idx = (u * p) & 127;
                float cc = cs[idx], ss = sn[idx];
                float xr = Xre[p][v], xi = Xim[p][v];
                re = fmaf(xr, cc, re); re = fmaf(xi, ss, re);
                im = fmaf(xi, cc, im); im = fmaf(-xr, ss, im);
            }
            int vv = v0 + v;
            int ur = u & 63;
            int choff = (u < 64) ? c : (576 + c);
            g_cat[cbase + (size_t)choff * 4096 + (ur << 6) + vv] = re;
            g_cat[cbase + (size_t)(choff + 288) * 4096 + (ur << 6) + vv] = im;
        }
    }
}

// ---------------- softmax over t (9) and gate with f ----------------
__global__ void softmax_wd_kernel() {
    int i = blockIdx.x * THREADS + threadIdx.x;
    if (i >= 2097152) return;
    int n = i & 4095;
    int cb = i >> 12;
    int c = cb & 63, b = cb >> 6;
    size_t base = (size_t)(b * 576 + c * 9) * 4096 + n;
    float w[9];
    float mx = -3.4e38f;
    #pragma unroll
    for (int t = 0; t < 9; t++) { w[t] = g_weight[base + t * 4096]; mx = fmaxf(mx, w[t]); }
    float sum = 0.f;
    #pragma unroll
    for (int t = 0; t < 9; t++) { w[t] = expf(w[t] - mx); sum += w[t]; }
    float inv = 1.f / sum;
    #pragma unroll
    for (int t = 0; t < 9; t++)
        g_wd[base + t * 4096] = g_f[base + t * 4096] * w[t] * inv;
}

// ---------------- generic fp32 GEMM: C(MxN) = A(MxK,row) @ B(KxN,row) + epilogue ----------------
// mode 0: none; mode 1: silu(v*g1+b1); mode 2: relu(silu(v*g1+b1)*g2+b2)
// Requirements: K % 16 == 0, N % 128 == 0. M arbitrary (guarded).
__global__ __launch_bounds__(256) void sgemm_kernel(
    const float* __restrict__ A, const float* __restrict__ B, float* __restrict__ C,
    int M, int N, int K,
    long long sA, long long sB, long long sC,
    const float* __restrict__ G1, const float* __restrict__ Bi1,
    const float* __restrict__ G2, const float* __restrict__ Bi2, int mode)
{
    __shared__ float As[16][128];
    __shared__ float Bs[16][128];
    int tid = threadIdx.x;
    int bn0 = blockIdx.x << 7, bm0 = blockIdx.y << 7;
    A += (long long)blockIdx.z * sA;
    B += (long long)blockIdx.z * sB;
    C += (long long)blockIdx.z * sC;

    int aRow = tid >> 1;
    int aK   = (tid & 1) << 3;
    int bRow = tid >> 5;
    int bCol = (tid & 31) << 2;
    int ty = tid >> 4, tx = tid & 15;

    float acc[8][8];
    #pragma unroll
    for (int i = 0; i < 8; i++)
        #pragma unroll
        for (int j = 0; j < 8; j++) acc[i][j] = 0.f;

    int mA = bm0 + aRow;
    bool aOk = (mA < M);
    const float* Ap = A + (long long)(aOk ? mA : 0) * K + aK;
    const float* Bp = B + (long long)bRow * N + bn0 + bCol;

    for (int k0 = 0; k0 < K; k0 += 16) {
        float4 a0, a1;
        if (aOk) {
            a0 = *(const float4*)(Ap + k0);
            a1 = *(const float4*)(Ap + k0 + 4);
        } else {
            a0 = make_float4(0.f, 0.f, 0.f, 0.f);
            a1 = a0;
        }
        float4 b0 = *(const float4*)(Bp + (long long)k0 * N);
        float4 b1 = *(const float4*)(Bp + (long long)(k0 + 8) * N);
        As[aK + 0][aRow] = a0.x; As[aK + 1][aRow] = a0.y;
        As[aK + 2][aRow] = a0.z; As[aK + 3][aRow] = a0.w;
        As[aK + 4][aRow] = a1.x; As[aK + 5][aRow] = a1.y;
        As[aK + 6][aRow] = a1.z; As[aK + 7][aRow] = a1.w;
        *(float4*)&Bs[bRow][bCol]     = b0;
        *(float4*)&Bs[bRow + 8][bCol] = b1;
        __syncthreads();
        #pragma unroll
        for (int k = 0; k < 16; k++) {
            float4 av0 = *(const float4*)&As[k][ty << 3];
            float4 av1 = *(const float4*)&As[k][(ty << 3) + 4];
            float4 bv0 = *(const float4*)&Bs[k][tx << 3];
            float4 bv1 = *(const float4*)&Bs[k][(tx << 3) + 4];
            float av[8] = {av0.x, av0.y, av0.z, av0.w, av1.x, av1.y, av1.z, av1.w};
            float bv[8] = {bv0.x, bv0.y, bv0.z, bv0.w, bv1.x, bv1.y, bv1.z, bv1.w};
            #pragma unroll
            for (int i = 0; i < 8; i++)
                #pragma unroll
                for (int j = 0; j < 8; j++)
                    acc[i][j] = fmaf(av[i], bv[j], acc[i][j]);
        }
        __syncthreads();
    }

    int n0 = bn0 + (tx << 3);
    #pragma unroll
    for (int i = 0; i < 8; i++) {
        int m = bm0 + (ty << 3) + i;
        if (m >= M) break;
        float g1v = 0.f, b1v = 0.f, g2v = 0.f, b2v = 0.f;
        if (mode >= 1) { g1v = G1[m]; b1v = Bi1[m]; }
        if (mode == 2) { g2v = G2[m]; b2v = Bi2[m]; }
        float o[8];
        #pragma unroll
        for (int j = 0; j < 8; j++) {
            float v = acc[i][j];
            if (mode >= 1) {
                float t = v * g1v + b1v;
                v = t / (1.f + expf(-t));
                if (mode == 2) {
                    float u2 = v * g2v + b2v;
                    v = u2 > 0.f ? u2 : 0.f;
                }
            }
            o[j] = v;
        }
        float4* Cp = (float4*)&C[(long long)m * N + n0];
        Cp[0] = make_float4(o[0], o[1], o[2], o[3]);
        Cp[1] = make_float4(o[4], o[5], o[6], o[7]);
    }
}

// ---------------- host ----------------
extern "C" void kernel_launch(void* const* d_in, const int* in_sizes, int n_in,
                              void* d_out, int out_size) {
    const float* x     = (const float*)d_in[0];
    const float* w_gw  = (const float*)d_in[1];
    const float* gg    = (const float*)d_in[2];
    const float* bg    = (const float*)d_in[3];
    const float* w_fm  = (const float*)d_in[4];
    const float* gfm   = (const float*)d_in[5];
    const float* bfm   = (const float*)d_in[6];
    const float* w_cv2 = (const float*)d_in[7];
    const float* gcv   = (const float*)d_in[8];
    const float* bcv   = (const float*)d_in[9];
    const float* w_gf  = (const float*)d_in[10];
    const float* ggf   = (const float*)d_in[11];
    const float* bgf   = (const float*)d_in[12];
    const float* ggf2  = (const float*)d_in[13];
    const float* bgf2  = (const float*)d_in[14];
    const float* w_out = (const float*)d_in[15];
    float* out = (float*)d_out;

    float *p_spd, *p_w0, *p_pool, *p_X1, *p_cat, *p_mp, *p_weight, *p_f, *p_wd, *p_col, *p_tw;
    cudaGetSymbolAddress((void**)&p_spd,    g_spd);
    cudaGetSymbolAddress((void**)&p_w0,     g_w0);
    cudaGetSymbolAddress((void**)&p_pool,   g_pool);
    cudaGetSymbolAddress((void**)&p_X1,     g_X1);
    cudaGetSymbolAddress((void**)&p_cat,    g_cat);
    cudaGetSymbolAddress((void**)&p_mp,     g_mp);
    cudaGetSymbolAddress((void**)&p_weight, g_weight);
    cudaGetSymbolAddress((void**)&p_f,      g_f);
    cudaGetSymbolAddress((void**)&p_wd,     g_wd);
    cudaGetSymbolAddress((void**)&p_col,    g_col);
    cudaGetSymbolAddress((void**)&p_tw,     g_tw);

    init_tw_kernel<<<64, 256>>>();
    spd_kernel<<<131072, 256>>>(x);

    // conv_gw: per-batch (576x256) @ (256x16384), silu(bn)
    {
        dim3 g(128, 5, 8);
        sgemm_kernel<<<g, 256>>>(w_gw, p_spd, p_w0, 576, 16384, 256,
                                 0LL, 256LL * 16384, 576LL * 16384,
                                 gg, bg, nullptr, nullptr, 1);
    }
    avgpool_kernel<<<294912, 256>>>();

    // row rfft as GEMM: per-batch (36864x128) @ (128x128 twiddle)
    {
        dim3 g(1, 288, 8);
        sgemm_kernel<<<g, 256>>>(p_pool, p_tw, p_X1, 36864, 128, 128,
                                 576LL * 16384, 0LL, 288LL * 16384,
                                 nullptr, nullptr, nullptr, nullptr, 0);
    }
    fft_col_kernel<<<2304, 256>>>();

    // conv_fm: per-batch (288x1152) @ (1152x4096) -> weight[:,0:288]
    {
        dim3 g(32, 3, 8);
        sgemm_kernel<<<g, 256>>>(w_fm, p_cat, p_weight, 288, 4096, 1152,
                                 0LL, 1152LL * 4096, 576LL * 4096,
                                 gfm, bfm, nullptr, nullptr, 1);
    }
    maxpool_kernel<<<36864, 256>>>();

    // conv_cv2: per-batch (288x288) @ (288x4096) -> weight[:,288:576]
    {
        dim3 g(32, 3, 8);
        sgemm_kernel<<<g, 256>>>(w_cv2, p_mp, p_weight + 288 * 4096, 288, 4096, 288,
                                 0LL, 288LL * 4096, 576LL * 4096,
                                 gcv, bcv, nullptr, nullptr, 1);
    }
    im2col_kernel<<<294912, 256>>>();

    // conv_gf: per-batch (576x2304) @ (2304x4096), relu(bn2(silu(bn1)))
    {
        dim3 g(32, 5, 8);
        sgemm_kernel<<<g, 256>>>(w_gf, p_col, p_f, 576, 4096, 2304,
                                 0LL, 2304LL * 4096, 576LL * 4096,
                                 ggf, bgf, ggf2, bgf2, 2);
    }
    softmax_wd_kernel<<<8192, 256>>>();

    // final (pixel-shuffle + stride-3 conv collapsed): (128x576) @ (576x4096)
    {
        dim3 g(32, 1, 8);
        sgemm_kernel<<<g, 256>>>(w_out, p_wd, out, 128, 4096, 576,
                                 0LL, 576LL * 4096, 128LL * 4096,
                                 nullptr, nullptr, nullptr, nullptr, 0);
    }
}

// round 3
// speedup vs baseline: 1.5192x; 1.5183x over previous
#include <cuda_runtime.h>
#include <cuda_bf16.h>
#include <stdint.h>
#include <math.h>

#define THREADS 256

// ---------------- scratch ----------------
__device__ float g_spd[33554432];     // (8,256,128,128)
__device__ float g_w0[75497472];      // (8,576,128,128)
__device__ float g_pool[75497472];    // (8,576,128,128)
__device__ float g_X1[37748736];      // (8,288,128,128)
__device__ float g_cat[37748736];     // (8,1152,64,64)
__device__ float g_mp[9437184];       // (8,288,64,64)
__device__ float g_weight[18874368];  // (8,576,64,64)
__device__ float g_f[18874368];       // (8,576,64,64)
__device__ float g_wd[18874368];      // (8,576,64,64)
__device__ float g_col[75497472];     // (8,2304,64,64)
__device__ float g_tw[16384];
__device__ float g_ct[128];
__device__ float g_st[128];

__global__ void init_tw_kernel() {
    int i = blockIdx.x * blockDim.x + threadIdx.x;
    const double TWO_PI = 6.283185307179586476925286766559;
    if (i < 16384) {
        int q = i >> 7, v = i & 127;
        if (v < 64)
            g_tw[i] = (float)cos(TWO_PI * (double)((q * v) & 127) / 128.0);
        else
            g_tw[i] = (float)(-sin(TWO_PI * (double)((q * (v - 64)) & 127) / 128.0));
    }
    if (i < 128) {
        g_ct[i] = (float)cos(TWO_PI * (double)i / 128.0);
        g_st[i] = (float)sin(TWO_PI * (double)i / 128.0);
    }
}

__global__ void spd_kernel(const float* __restrict__ x) {
    int i = blockIdx.x * THREADS + threadIdx.x;
    if (i >= 33554432) return;
    int q = i & 127, p = (i >> 7) & 127, s = (i >> 14) & 255, b = i >> 22;
    int quad = s >> 6, c = s & 63;
    int r  = 2 * p + (quad & 1);
    int cc = 2 * q + (quad >> 1);
    g_spd[i] = x[((size_t)(b * 64 + c) * 256 + r) * 256 + cc];
}

__global__ void avgpool_kernel() {
    int i = blockIdx.x * THREADS + threadIdx.x;
    if (i >= 75497472) return;
    int q = i & 127, p = (i >> 7) & 127;
    int cb = i >> 14;
    const float* s = g_w0 + (size_t)cb * 16384;
    float v = 0.f;
    if (p < 127 && q < 127) {
        int o = (p << 7) + q;
        v = 0.25f * (s[o] + s[o + 128] + s[o + 1] + s[o + 129]);
    }
    g_pool[i] = v;
}

__global__ void maxpool_kernel() {
    int i = blockIdx.x * THREADS + threadIdx.x;
    if (i >= 9437184) return;
    int v = i & 63, u = (i >> 6) & 63;
    int cb = i >> 12;
    int c = cb % 288, b = cb / 288;
    const float* s = g_pool + (size_t)(b * 576 + 288 + c) * 16384;
    int r0 = max(2 * u - 1, 0), r1 = min(2 * u + 1, 126);
    int c0 = max(2 * v - 1, 0), c1 = min(2 * v + 1, 126);
    float m = -3.4e38f;
    for (int r = r0; r <= r1; r++)
        for (int cc = c0; cc <= c1; cc++)
            m = fmaxf(m, s[(r << 7) + cc]);
    g_mp[i] = m;
}

__global__ void im2col_kernel() {
    int i = blockIdx.x * THREADS + threadIdx.x;
    if (i >= 75497472) return;
    int n = i & 4095;
    int v = n & 63, u = n >> 6;
    int kb = i >> 12;
    int k = kb % 2304, b = kb / 2304;
    int ic = k / 9, t = k - ic * 9;
    int di = t / 3, dj = t - di * 3;
    int r  = 2 * u + di - 1;
    int cc = 2 * v + dj - 1;
    float val = 0.f;
    if ((unsigned)r < 128u && (unsigned)cc < 128u)
        val = g_spd[((size_t)(b * 256 + ic) << 14) + (r << 7) + cc];
    g_col[i] = val;
}

__global__ __launch_bounds__(256) void fft_col_kernel() {
    __shared__ float Xre[128][32];
    __shared__ float Xim[128][32];
    __shared__ float cs[128], sn[128];
    int blk = blockIdx.x;
    int b = blk / 288, c = blk % 288;
    int tid = threadIdx.x;
    if (tid < 128) { cs[tid] = g_ct[tid]; sn[tid] = g_st[tid]; }
    const float* X1 = g_X1 + (size_t)(b * 288 + c) * 16384;
    size_t cbase = (size_t)b * 1152 * 4096;
    for (int half = 0; half < 2; half++) {
        int v0 = half << 5;
        __syncthreads();
        for (int e = tid; e < 4096; e += 256) {
            int p = e >> 5, v = e & 31;
            Xre[p][v] = X1[(p << 7) + v0 + v];
            Xim[p][v] = X1[(p << 7) + 64 + v0 + v];
        }
        __syncthreads();
        for (int r = 0; r < 16; r++) {
            int o = (r << 8) + tid;
            int u = o >> 5, v = o & 31;
            float re = 0.f, im = 0.f;
            #pragma unroll 8
            for (int p = 0; p < 128; p++) {
                int idx = (u * p) & 127;
                float cc = cs[idx], ss = sn[idx];
                float xr = Xre[p][v], xi = Xim[p][v];
                re = fmaf(xr, cc, re); re = fmaf(xi, ss, re);
                im = fmaf(xi, cc, im); im = fmaf(-xr, ss, im);
            }
            int vv = v0 + v;
            int ur = u & 63;
            int choff = (u < 64) ? c : (576 + c);
            g_cat[cbase + (size_t)choff * 4096 + (ur << 6) + vv] = re;
            g_cat[cbase + (size_t)(choff + 288) * 4096 + (ur << 6) + vv] = im;
        }
    }
}

__global__ void softmax_wd_kernel() {
    int i = blockIdx.x * THREADS + threadIdx.x;
    if (i >= 2097152) return;
    int n = i & 4095;
    int cb = i >> 12;
    int c = cb & 63, b = cb >> 6;
    size_t base = (size_t)(b * 576 + c * 9) * 4096 + n;
    float w[9];
    float mx = -3.4e38f;
    #pragma unroll
    for (int t = 0; t < 9; t++) { w[t] = g_weight[base + t * 4096]; mx = fmaxf(mx, w[t]); }
    float sum = 0.f;
    #pragma unroll
    for (int t = 0; t < 9; t++) { w[t] = expf(w[t] - mx); sum += w[t]; }
    float inv = 1.f / sum;
    #pragma unroll
    for (int t = 0; t < 9; t++)
        g_wd[base + t * 4096] = g_f[base + t * 4096] * w[t] * inv;
}

// ---------------- tensor-core GEMM with in-kernel bf16 hi/lo split ----------------
// C(MxN) = A(MxK,row) @ B(KxN,row), fp32 in/out, 3x bf16 mma passes.
// K%16==0, N covered exactly by 128-wide blocks. M guarded.
__device__ __forceinline__ void split2(float a, float b, uint32_t& hw, uint32_t& lw) {
    __nv_bfloat16 ah = __float2bfloat16(a), bh = __float2bfloat16(b);
    __nv_bfloat16 al = __float2bfloat16(a - __bfloat162float(ah));
    __nv_bfloat16 bl = __float2bfloat16(b - __bfloat162float(bh));
    hw = (uint32_t)*(uint16_t*)&ah | ((uint32_t)*(uint16_t*)&bh << 16);
    lw = (uint32_t)*(uint16_t*)&al | ((uint32_t)*(uint16_t*)&bl << 16);
}

#define MMA_BF16(d, a, b0_, b1_) \
    asm volatile("mma.sync.aligned.m16n8k16.row.col.f32.bf16.bf16.f32 " \
        "{%0,%1,%2,%3},{%4,%5,%6,%7},{%8,%9},{%0,%1,%2,%3};" \
        : "+f"(d[0]), "+f"(d[1]), "+f"(d[2]), "+f"(d[3]) \
        : "r"(a[0]), "r"(a[1]), "r"(a[2]), "r"(a[3]), "r"(b0_), "r"(b1_))

__global__ __launch_bounds__(256) void hgemm_kernel(
    const float* __restrict__ A, const float* __restrict__ B, float* __restrict__ C,
    int M, int N, int K,
    long long sA, long long sB, long long sC,
    const float* __restrict__ G1, const float* __restrict__ Bi1,
    const float* __restrict__ G2, const float* __restrict__ Bi2, int mode)
{
    // [stage][Ah,Al,Bh,Bl][row*9+word]; word = 2 bf16 along k. 36864 B total.
    __shared__ uint32_t sm[2][4][1152];
    int tid = threadIdx.x;
    int bn0 = blockIdx.x << 7, bm0 = blockIdx.y << 7;
    A += (long long)blockIdx.z * sA;
    B += (long long)blockIdx.z * sB;
    C += (long long)blockIdx.z * sC;

    int aRow = tid >> 1, aKh = tid & 1;               // A: m=aRow, k-half
    bool aOk = (bm0 + aRow) < M;
    const float* Ap = A + (long long)(aOk ? (bm0 + aRow) : 0) * K + aKh * 8;
    int bKp = tid >> 5, bN0 = (tid & 31) << 2;        // B: k-pair, 4 cols
    const float* Bp = B + (long long)(2 * bKp) * N + bn0 + bN0;

    int wid = tid >> 5, lane = tid & 31;
    int wm = (wid >> 2) << 6, wn = (wid & 3) << 5;    // warp tile 64x32
    int g = lane >> 2, tg = lane & 3;

    float acc[4][4][4];
    #pragma unroll
    for (int i = 0; i < 4; i++)
        #pragma unroll
        for (int j = 0; j < 4; j++)
            #pragma unroll
            for (int r = 0; r < 4; r++) acc[i][j][r] = 0.f;

    int nstage = K >> 4;

    // prologue: stage 0 -> sm[0]
    {
        float4 a0, a1;
        if (aOk) { a0 = *(const float4*)(Ap); a1 = *(const float4*)(Ap + 4); }
        else { a0 = make_float4(0.f,0.f,0.f,0.f); a1 = a0; }
        float4 b0 = *(const float4*)(Bp);
        float4 b1 = *(const float4*)(Bp + N);
        uint32_t h, l;
        int abase = aRow * 9 + aKh * 4;
        split2(a0.x, a0.y, h, l); sm[0][0][abase+0] = h; sm[0][1][abase+0] = l;
        split2(a0.z, a0.w, h, l); sm[0][0][abase+1] = h; sm[0][1][abase+1] = l;
        split2(a1.x, a1.y, h, l); sm[0][0][abase+2] = h; sm[0][1][abase+2] = l;
        split2(a1.z, a1.w, h, l); sm[0][0][abase+3] = h; sm[0][1][abase+3] = l;
        float bx[4] = {b0.x, b0.y, b0.z, b0.w};
        float by[4] = {b1.x, b1.y, b1.z, b1.w};
        #pragma unroll
        for (int i = 0; i < 4; i++) {
            split2(bx[i], by[i], h, l);
            sm[0][2][(bN0 + i) * 9 + bKp] = h;
            sm[0][3][(bN0 + i) * 9 + bKp] = l;
        }
    }

    int buf = 0;
    for (int s = 0; s < nstage; s++) {
        __syncthreads();
        float4 a0, a1, b0, b1;
        bool hasNext = (s + 1 < nstage);
        if (hasNext) {
            long long k0 = (long long)(s + 1) << 4;
            if (aOk) { a0 = *(const float4*)(Ap + k0); a1 = *(const float4*)(Ap + k0 + 4); }
            else { a0 = make_float4(0.f,0.f,0.f,0.f); a1 = a0; }
            b0 = *(const float4*)(Bp + k0 * N);
            b1 = *(const float4*)(Bp + (k0 + 1) * N);
        }
        // compute on sm[buf]
        uint32_t ah[4][4], al[4][4];
        #pragma unroll
        for (int mt = 0; mt < 4; mt++) {
            int r0 = (wm + (mt << 4) + g) * 9, r8 = r0 + 72;
            ah[mt][0] = sm[buf][0][r0 + tg];     ah[mt][1] = sm[buf][0][r8 + tg];
            ah[mt][2] = sm[buf][0][r0 + tg + 4]; ah[mt][3] = sm[buf][0][r8 + tg + 4];
            al[mt][0] = sm[buf][1][r0 + tg];     al[mt][1] = sm[buf][1][r8 + tg];
            al[mt][2] = sm[buf][1][r0 + tg + 4]; al[mt][3] = sm[buf][1][r8 + tg + 4];
        }
        #pragma unroll
        for (int nt = 0; nt < 4; nt++) {
            int rb = (wn + (nt << 3) + g) * 9;
            uint32_t bh0 = sm[buf][2][rb + tg], bh1 = sm[buf][2][rb + tg + 4];
            uint32_t bl0 = sm[buf][3][rb + tg], bl1 = sm[buf][3][rb + tg + 4];
            #pragma unroll
            for (int mt = 0; mt < 4; mt++) {
                MMA_BF16(acc[mt][nt], ah[mt], bh0, bh1);
                MMA_BF16(acc[mt][nt], ah[mt], bl0, bl1);
                MMA_BF16(acc[mt][nt], al[mt], bh0, bh1);
            }
        }
        if (hasNext) {
            int nb = buf ^ 1;
            uint32_t h, l;
            int abase = aRow * 9 + aKh * 4;
            split2(a0.x, a0.y, h, l); sm[nb][0][abase+0] = h; sm[nb][1][abase+0] = l;
            split2(a0.z, a0.w, h, l); sm[nb][0][abase+1] = h; sm[nb][1][abase+1] = l;
            split2(a1.x, a1.y, h, l); sm[nb][0][abase+2] = h; sm[nb][1][abase+2] = l;
            split2(a1.z, a1.w, h, l); sm[nb][0][abase+3] = h; sm[nb][1][abase+3] = l;
            float bx[4] = {b0.x, b0.y, b0.z, b0.w};
            float by[4] = {b1.x, b1.y, b1.z, b1.w};
            #pragma unroll
            for (int i = 0; i < 4; i++) {
                split2(bx[i], by[i], h, l);
                sm[nb][2][(bN0 + i) * 9 + bKp] = h;
                sm[nb][3][(bN0 + i) * 9 + bKp] = l;
            }
        }
        buf ^= 1;
    }

    // epilogue
    #pragma unroll
    for (int mt = 0; mt < 4; mt++) {
        int mbase = bm0 + wm + (mt << 4) + g;
        #pragma unroll
        for (int half = 0; half < 2; half++) {
            int m = mbase + half * 8;
            if (m >= M) continue;
            float g1v = 0.f, b1v = 0.f, g2v = 0.f, b2v = 0.f;
            if (mode >= 1) { g1v = G1[m]; b1v = Bi1[m]; }
            if (mode == 2) { g2v = G2[m]; b2v = Bi2[m]; }
            #pragma unroll
            for (int nt = 0; nt < 4; nt++) {
                float v0 = acc[mt][nt][half * 2 + 0];
                float v1 = acc[mt][nt][half * 2 + 1];
                if (mode >= 1) {
                    float t0 = v0 * g1v + b1v;
                    float t1 = v1 * g1v + b1v;
                    v0 = t0 / (1.f + expf(-t0));
                    v1 = t1 / (1.f + expf(-t1));
                    if (mode == 2) {
                        float u0 = v0 * g2v + b2v, u1 = v1 * g2v + b2v;
                        v0 = u0 > 0.f ? u0 : 0.f;
                        v1 = u1 > 0.f ? u1 : 0.f;
                    }
                }
                int n = bn0 + wn + (nt << 3) + 2 * tg;
                *(float2*)&C[(long long)m * N + n] = make_float2(v0, v1);
            }
        }
    }
}

// ---------------- host ----------------
extern "C" void kernel_launch(void* const* d_in, const int* in_sizes, int n_in,
                              void* d_out, int out_size) {
    const float* x     = (const float*)d_in[0];
    const float* w_gw  = (const float*)d_in[1];
    const float* gg    = (const float*)d_in[2];
    const float* bg    = (const float*)d_in[3];
    const float* w_fm  = (const float*)d_in[4];
    const float* gfm   = (const float*)d_in[5];
    const float* bfm   = (const float*)d_in[6];
    const float* w_cv2 = (const float*)d_in[7];
    const float* gcv   = (const float*)d_in[8];
    const float* bcv   = (const float*)d_in[9];
    const float* w_gf  = (const float*)d_in[10];
    const float* ggf   = (const float*)d_in[11];
    const float* bgf   = (const float*)d_in[12];
    const float* ggf2  = (const float*)d_in[13];
    const float* bgf2  = (const float*)d_in[14];
    const float* w_out = (const float*)d_in[15];
    float* out = (float*)d_out;

    float *p_spd, *p_w0, *p_pool, *p_X1, *p_cat, *p_mp, *p_weight, *p_f, *p_wd, *p_col, *p_tw;
    cudaGetSymbolAddress((void**)&p_spd,    g_spd);
    cudaGetSymbolAddress((void**)&p_w0,     g_w0);
    cudaGetSymbolAddress((void**)&p_pool,   g_pool);
    cudaGetSymbolAddress((void**)&p_X1,     g_X1);
    cudaGetSymbolAddress((void**)&p_cat,    g_cat);
    cudaGetSymbolAddress((void**)&p_mp,     g_mp);
    cudaGetSymbolAddress((void**)&p_weight, g_weight);
    cudaGetSymbolAddress((void**)&p_f,      g_f);
    cudaGetSymbolAddress((void**)&p_wd,     g_wd);
    cudaGetSymbolAddress((void**)&p_col,    g_col);
    cudaGetSymbolAddress((void**)&p_tw,     g_tw);

    init_tw_kernel<<<64, 256>>>();
    spd_kernel<<<131072, 256>>>(x);

    // conv_gw: per-batch (576x256) @ (256x16384), silu(bn)
    {
        dim3 g(128, 5, 8);
        hgemm_kernel<<<g, 256>>>(w_gw, p_spd, p_w0, 576, 16384, 256,
                                 0LL, 256LL * 16384, 576LL * 16384,
                                 gg, bg, nullptr, nullptr, 1);
    }
    avgpool_kernel<<<294912, 256>>>();

    // row rfft as GEMM: per-batch (36864x128) @ (128x128 twiddle)
    {
        dim3 g(1, 288, 8);
        hgemm_kernel<<<g, 256>>>(p_pool, p_tw, p_X1, 36864, 128, 128,
                                 576LL * 16384, 0LL, 288LL * 16384,
                                 nullptr, nullptr, nullptr, nullptr, 0);
    }
    fft_col_kernel<<<2304, 256>>>();

    // conv_fm: per-batch (288x1152) @ (1152x4096)
    {
        dim3 g(32, 3, 8);
        hgemm_kernel<<<g, 256>>>(w_fm, p_cat, p_weight, 288, 4096, 1152,
                                 0LL, 1152LL * 4096, 576LL * 4096,
                                 gfm, bfm, nullptr, nullptr, 1);
    }
    maxpool_kernel<<<36864, 256>>>();

    // conv_cv2: per-batch (288x288) @ (288x4096)
    {
        dim3 g(32, 3, 8);
        hgemm_kernel<<<g, 256>>>(w_cv2, p_mp, p_weight + 288 * 4096, 288, 4096, 288,
                                 0LL, 288LL * 4096, 576LL * 4096,
                                 gcv, bcv, nullptr, nullptr, 1);
    }
    im2col_kernel<<<294912, 256>>>();

    // conv_gf: per-batch (576x2304) @ (2304x4096)
    {
        dim3 g(32, 5, 8);
        hgemm_kernel<<<g, 256>>>(w_gf, p_col, p_f, 576, 4096, 2304,
                                 0LL, 2304LL * 4096, 576LL * 4096,
                                 ggf, bgf, ggf2, bgf2, 2);
    }
    softmax_wd_kernel<<<8192, 256>>>();

    // final collapsed conv: (128x576) @ (576x4096)
    {
        dim3 g(32, 1, 8);
        hgemm_kernel<<<g, 256>>>(w_out, p_wd, out, 128, 4096, 576,
                                 0LL, 576LL * 4096, 128LL * 4096,
                                 nullptr, nullptr, nullptr, nullptr, 0);
    }
}

// round 4
// speedup vs baseline: 1.9593x; 1.2897x over previous
#include <cuda_runtime.h>
#include <cuda_bf16.h>
#include <stdint.h>
#include <math.h>

#define THREADS 256

// ---------------- scratch ----------------
__device__ float g_spd[33554432];     // (8,256,128,128)
__device__ float g_w0[75497472];      // (8,576,128,128)
__device__ float g_pool[75497472];    // (8,576,128,128)
__device__ float g_X1[37748736];      // (8,288,128,128)
__device__ float g_cat[37748736];     // (8,1152,64,64)
__device__ float g_mp[9437184];       // (8,288,64,64)
__device__ float g_weight[18874368];  // (8,576,64,64)
__device__ float g_f[18874368];       // (8,576,64,64)
__device__ float g_wd[18874368];      // (8,576,64,64)
__device__ float g_col[75497472];     // (8,2304,64,64)
__device__ float g_tw[16384];
__device__ float g_ct[128];
__device__ float g_st[128];

__global__ void init_tw_kernel() {
    int i = blockIdx.x * blockDim.x + threadIdx.x;
    const double TWO_PI = 6.283185307179586476925286766559;
    if (i < 16384) {
        int q = i >> 7, v = i & 127;
        if (v < 64)
            g_tw[i] = (float)cos(TWO_PI * (double)((q * v) & 127) / 128.0);
        else
            g_tw[i] = (float)(-sin(TWO_PI * (double)((q * (v - 64)) & 127) / 128.0));
    }
    if (i < 128) {
        g_ct[i] = (float)cos(TWO_PI * (double)i / 128.0);
        g_st[i] = (float)sin(TWO_PI * (double)i / 128.0);
    }
}

__global__ void spd_kernel(const float* __restrict__ x) {
    int i = blockIdx.x * THREADS + threadIdx.x;
    if (i >= 33554432) return;
    int q = i & 127, p = (i >> 7) & 127, s = (i >> 14) & 255, b = i >> 22;
    int quad = s >> 6, c = s & 63;
    int r  = 2 * p + (quad & 1);
    int cc = 2 * q + (quad >> 1);
    g_spd[i] = x[((size_t)(b * 64 + c) * 256 + r) * 256 + cc];
}

// ---------------- 2x2 stride-1 avg, float4: 4 outputs/thread ----------------
__global__ void avgpool_kernel() {
    int i = blockIdx.x * THREADS + threadIdx.x;
    if (i >= 18874368) return;
    int q4 = (i & 31) << 2;
    int p  = (i >> 5) & 127;
    int cb = i >> 12;
    float4 o = make_float4(0.f, 0.f, 0.f, 0.f);
    if (p < 127) {
        const float* s = g_w0 + ((size_t)cb << 14);
        int ofs = (p << 7) + q4;
        float4 a = *(const float4*)(s + ofs);
        float4 b = *(const float4*)(s + ofs + 128);
        o.x = 0.25f * (a.x + a.y + b.x + b.y);
        o.y = 0.25f * (a.y + a.z + b.y + b.z);
        o.z = 0.25f * (a.z + a.w + b.z + b.w);
        if (q4 < 124) {
            float a4 = s[ofs + 4], b4 = s[ofs + 132];
            o.w = 0.25f * (a.w + a4 + b.w + b4);
        }
    }
    *(float4*)(g_pool + ((size_t)cb << 14) + (p << 7) + q4) = o;
}

__global__ void maxpool_kernel() {
    int i = blockIdx.x * THREADS + threadIdx.x;
    if (i >= 9437184) return;
    int v = i & 63, u = (i >> 6) & 63;
    int cb = i >> 12;
    int c = cb % 288, b = cb / 288;
    const float* s = g_pool + (size_t)(b * 576 + 288 + c) * 16384;
    int r0 = max(2 * u - 1, 0), r1 = min(2 * u + 1, 126);
    int c0 = max(2 * v - 1, 0), c1 = min(2 * v + 1, 126);
    float m = -3.4e38f;
    for (int r = r0; r <= r1; r++)
        for (int cc = c0; cc <= c1; cc++)
            m = fmaxf(m, s[(r << 7) + cc]);
    g_mp[i] = m;
}

__global__ void im2col_kernel() {
    int i = blockIdx.x * THREADS + threadIdx.x;
    if (i >= 75497472) return;
    int n = i & 4095;
    int v = n & 63, u = n >> 6;
    int kb = i >> 12;
    int k = kb % 2304, b = kb / 2304;
    int ic = k / 9, t = k - ic * 9;
    int di = t / 3, dj = t - di * 3;
    int r  = 2 * u + di - 1;
    int cc = 2 * v + dj - 1;
    float val = 0.f;
    if ((unsigned)r < 128u && (unsigned)cc < 128u)
        val = g_spd[((size_t)(b * 256 + ic) << 14) + (r << 7) + cc];
    g_col[i] = val;
}

// ---------------- column FFT, radix-4: X[u],X[u+32],X[u+64],X[u+96] per pass ----------------
__global__ __launch_bounds__(256) void fft_col_kernel() {
    __shared__ float Xre[128][32];
    __shared__ float Xim[128][32];
    __shared__ float cs[128], sn[128];
    int blk = blockIdx.x;
    int b = blk / 288, c = blk % 288;
    int tid = threadIdx.x;
    if (tid < 128) { cs[tid] = g_ct[tid]; sn[tid] = g_st[tid]; }
    const float* X1 = g_X1 + (size_t)(b * 288 + c) * 16384;
    size_t cbase = (size_t)b * 1152 * 4096;
    size_t oRe  = cbase + (size_t)c * 4096;
    size_t oIm  = oRe  + (size_t)288 * 4096;
    size_t oHRe = cbase + (size_t)(576 + c) * 4096;
    size_t oHIm = oHRe + (size_t)288 * 4096;
    for (int half = 0; half < 2; half++) {
        int v0 = half << 5;
        __syncthreads();
        for (int e = tid; e < 4096; e += 256) {
            int p = e >> 5, v = e & 31;
            Xre[p][v] = X1[(p << 7) + v0 + v];
            Xim[p][v] = X1[(p << 7) + 64 + v0 + v];
        }
        __syncthreads();
        for (int r = 0; r < 4; r++) {
            int item = (r << 8) + tid;          // 0..1023
            int u = item >> 5, v = item & 31;   // u in 0..31
            float r0 = 0.f, i0 = 0.f, r1 = 0.f, i1 = 0.f;
            float r2 = 0.f, i2 = 0.f, r3 = 0.f, i3 = 0.f;
            int u1 = u, u2 = (2 * u) & 127, u3 = (3 * u) & 127, u4 = (4 * u) & 127;
            int idx = 0;
            #pragma unroll 4
            for (int p = 0; p < 128; p += 4) {
                {
                    float cc = cs[idx], ss = sn[idx];
                    float xr = Xre[p][v], xi = Xim[p][v];
                    r0 = fmaf(xr, cc, r0); r0 = fmaf(xi, ss, r0);
                    i0 = fmaf(xi, cc, i0); i0 = fmaf(-xr, ss, i0);
                }
                {
                    int id = (idx + u1) & 127;
                    float cc = cs[id], ss = sn[id];
                    float xr = Xre[p + 1][v], xi = Xim[p + 1][v];
                    r1 = fmaf(xr, cc, r1); r1 = fmaf(xi, ss, r1);
                    i1 = fmaf(xi, cc, i1); i1 = fmaf(-xr, ss, i1);
                }
                {
                    int id = (idx + u2) & 127;
                    float cc = cs[id], ss = sn[id];
                    float xr = Xre[p + 2][v], xi = Xim[p + 2][v];
                    r2 = fmaf(xr, cc, r2); r2 = fmaf(xi, ss, r2);
                    i2 = fmaf(xi, cc, i2); i2 = fmaf(-xr, ss, i2);
                }
                {
                    int id = (idx + u3) & 127;
                    float cc = cs[id], ss = sn[id];
                    float xr = Xre[p + 3][v], xi = Xim[p + 3][v];
                    r3 = fmaf(xr, cc, r3); r3 = fmaf(xi, ss, r3);
                    i3 = fmaf(xi, cc, i3); i3 = fmaf(-xr, ss, i3);
                }
                idx = (idx + u4) & 127;
            }
            float rA = r0 + r2, iA = i0 + i2;
            float rB = r0 - r2, iB = i0 - i2;
            float rC = r1 + r3, iC = i1 + i3;
            float rD = r1 - r3, iD = i1 - i3;
            int vv = v0 + v;
            int off_u   = (u << 6) + vv;
            int off_u32 = ((u + 32) << 6) + vv;
            g_cat[oRe  + off_u]   = rA + rC;  g_cat[oIm  + off_u]   = iA + iC;
            g_cat[oRe  + off_u32] = rB + iD;  g_cat[oIm  + off_u32] = iB - rD;
            g_cat[oHRe + off_u]   = rA - rC;  g_cat[oHIm + off_u]   = iA - iC;
            g_cat[oHRe + off_u32] = rB - iD;  g_cat[oHIm + off_u32] = iB + rD;
        }
    }
}

__global__ void softmax_wd_kernel() {
    int i = blockIdx.x * THREADS + threadIdx.x;
    if (i >= 2097152) return;
    int n = i & 4095;
    int cb = i >> 12;
    int c = cb & 63, b = cb >> 6;
    size_t base = (size_t)(b * 576 + c * 9) * 4096 + n;
    float w[9];
    float mx = -3.4e38f;
    #pragma unroll
    for (int t = 0; t < 9; t++) { w[t] = g_weight[base + t * 4096]; mx = fmaxf(mx, w[t]); }
    float sum = 0.f;
    #pragma unroll
    for (int t = 0; t < 9; t++) { w[t] = expf(w[t] - mx); sum += w[t]; }
    float inv = 1.f / sum;
    #pragma unroll
    for (int t = 0; t < 9; t++)
        g_wd[base + t * 4096] = g_f[base + t * 4096] * w[t] * inv;
}

// ---------------- tensor-core GEMM with in-kernel bf16 hi/lo split ----------------
__device__ __forceinline__ void split2(float a, float b, uint32_t& hw, uint32_t& lw) {
    __nv_bfloat16 ah = __float2bfloat16(a), bh = __float2bfloat16(b);
    __nv_bfloat16 al = __float2bfloat16(a - __bfloat162float(ah));
    __nv_bfloat16 bl = __float2bfloat16(b - __bfloat162float(bh));
    hw = (uint32_t)*(uint16_t*)&ah | ((uint32_t)*(uint16_t*)&bh << 16);
    lw = (uint32_t)*(uint16_t*)&al | ((uint32_t)*(uint16_t*)&bl << 16);
}

#define MMA_BF16(d, a, b0_, b1_) \
    asm volatile("mma.sync.aligned.m16n8k16.row.col.f32.bf16.bf16.f32 " \
        "{%0,%1,%2,%3},{%4,%5,%6,%7},{%8,%9},{%0,%1,%2,%3};" \
        : "+f"(d[0]), "+f"(d[1]), "+f"(d[2]), "+f"(d[3]) \
        : "r"(a[0]), "r"(a[1]), "r"(a[2]), "r"(a[3]), "r"(b0_), "r"(b1_))

__global__ __launch_bounds__(256) void hgemm_kernel(
    const float* __restrict__ A, const float* __restrict__ B, float* __restrict__ C,
    int M, int N, int K,
    long long sA, long long sB, long long sC,
    const float* __restrict__ G1, const float* __restrict__ Bi1,
    const float* __restrict__ G2, const float* __restrict__ Bi2, int mode)
{
    __shared__ uint32_t sm[2][4][1152];
    int tid = threadIdx.x;
    int bn0 = blockIdx.x << 7, bm0 = blockIdx.y << 7;
    A += (long long)blockIdx.z * sA;
    B += (long long)blockIdx.z * sB;
    C += (long long)blockIdx.z * sC;

    int aRow = tid >> 1, aKh = tid & 1;
    bool aOk = (bm0 + aRow) < M;
    const float* Ap = A + (long long)(aOk ? (bm0 + aRow) : 0) * K + aKh * 8;
    int bKp = tid >> 5, bN0 = (tid & 31) << 2;
    const float* Bp = B + (long long)(2 * bKp) * N + bn0 + bN0;

    int wid = tid >> 5, lane = tid & 31;
    int wm = (wid >> 2) << 6, wn = (wid & 3) << 5;
    int g = lane >> 2, tg = lane & 3;

    float acc[4][4][4];
    #pragma unroll
    for (int i = 0; i < 4; i++)
        #pragma unroll
        for (int j = 0; j < 4; j++)
            #pragma unroll
            for (int r = 0; r < 4; r++) acc[i][j][r] = 0.f;

    int nstage = K >> 4;

    {
        float4 a0, a1;
        if (aOk) { a0 = *(const float4*)(Ap); a1 = *(const float4*)(Ap + 4); }
        else { a0 = make_float4(0.f,0.f,0.f,0.f); a1 = a0; }
        float4 b0 = *(const float4*)(Bp);
        float4 b1 = *(const float4*)(Bp + N);
        uint32_t h, l;
        int abase = aRow * 9 + aKh * 4;
        split2(a0.x, a0.y, h, l); sm[0][0][abase+0] = h; sm[0][1][abase+0] = l;
        split2(a0.z, a0.w, h, l); sm[0][0][abase+1] = h; sm[0][1][abase+1] = l;
        split2(a1.x, a1.y, h, l); sm[0][0][abase+2] = h; sm[0][1][abase+2] = l;
        split2(a1.z, a1.w, h, l); sm[0][0][abase+3] = h; sm[0][1][abase+3] = l;
        float bx[4] = {b0.x, b0.y, b0.z, b0.w};
        float by[4] = {b1.x, b1.y, b1.z, b1.w};
        #pragma unroll
        for (int i = 0; i < 4; i++) {
            split2(bx[i], by[i], h, l);
            sm[0][2][(bN0 + i) * 9 + bKp] = h;
            sm[0][3][(bN0 + i) * 9 + bKp] = l;
        }
    }

    int buf = 0;
    for (int s = 0; s < nstage; s++) {
        __syncthreads();
        float4 a0, a1, b0, b1;
        bool hasNext = (s + 1 < nstage);
        if (hasNext) {
            long long k0 = (long long)(s + 1) << 4;
            if (aOk) { a0 = *(const float4*)(Ap + k0); a1 = *(const float4*)(Ap + k0 + 4); }
            else { a0 = make_float4(0.f,0.f,0.f,0.f); a1 = a0; }
            b0 = *(const float4*)(Bp + k0 * N);
            b1 = *(const float4*)(Bp + (k0 + 1) * N);
        }
        uint32_t ah[4][4], al[4][4];
        #pragma unroll
        for (int mt = 0; mt < 4; mt++) {
            int r0 = (wm + (mt << 4) + g) * 9, r8 = r0 + 72;
            ah[mt][0] = sm[buf][0][r0 + tg];     ah[mt][1] = sm[buf][0][r8 + tg];
            ah[mt][2] = sm[buf][0][r0 + tg + 4]; ah[mt][3] = sm[buf][0][r8 + tg + 4];
            al[mt][0] = sm[buf][1][r0 + tg];     al[mt][1] = sm[buf][1][r8 + tg];
            al[mt][2] = sm[buf][1][r0 + tg + 4]; al[mt][3] = sm[buf][1][r8 + tg + 4];
        }
        #pragma unroll
        for (int nt = 0; nt < 4; nt++) {
            int rb = (wn + (nt << 3) + g) * 9;
            uint32_t bh0 = sm[buf][2][rb + tg], bh1 = sm[buf][2][rb + tg + 4];
            uint32_t bl0 = sm[buf][3][rb + tg], bl1 = sm[buf][3][rb + tg + 4];
            #pragma unroll
            for (int mt = 0; mt < 4; mt++) {
                MMA_BF16(acc[mt][nt], ah[mt], bh0, bh1);
                MMA_BF16(acc[mt][nt], ah[mt], bl0, bl1);
                MMA_BF16(acc[mt][nt], al[mt], bh0, bh1);
            }
        }
        if (hasNext) {
            int nb = buf ^ 1;
            uint32_t h, l;
            int abase = aRow * 9 + aKh * 4;
            split2(a0.x, a0.y, h, l); sm[nb][0][abase+0] = h; sm[nb][1][abase+0] = l;
            split2(a0.z, a0.w, h, l); sm[nb][0][abase+1] = h; sm[nb][1][abase+1] = l;
            split2(a1.x, a1.y, h, l); sm[nb][0][abase+2] = h; sm[nb][1][abase+2] = l;
            split2(a1.z, a1.w, h, l); sm[nb][0][abase+3] = h; sm[nb][1][abase+3] = l;
            float bx[4] = {b0.x, b0.y, b0.z, b0.w};
            float by[4] = {b1.x, b1.y, b1.z, b1.w};
            #pragma unroll
            for (int i = 0; i < 4; i++) {
                split2(bx[i], by[i], h, l);
                sm[nb][2][(bN0 + i) * 9 + bKp] = h;
                sm[nb][3][(bN0 + i) * 9 + bKp] = l;
            }
        }
        buf ^= 1;
    }

    #pragma unroll
    for (int mt = 0; mt < 4; mt++) {
        int mbase = bm0 + wm + (mt << 4) + g;
        #pragma unroll
        for (int half = 0; half < 2; half++) {
            int m = mbase + half * 8;
            if (m >= M) continue;
            float g1v = 0.f, b1v = 0.f, g2v = 0.f, b2v = 0.f;
            if (mode >= 1) { g1v = G1[m]; b1v = Bi1[m]; }
            if (mode == 2) { g2v = G2[m]; b2v = Bi2[m]; }
            #pragma unroll
            for (int nt = 0; nt < 4; nt++) {
                float v0 = acc[mt][nt][half * 2 + 0];
                float v1 = acc[mt][nt][half * 2 + 1];
                if (mode >= 1) {
                    float t0 = v0 * g1v + b1v;
                    float t1 = v1 * g1v + b1v;
                    v0 = t0 / (1.f + expf(-t0));
                    v1 = t1 / (1.f + expf(-t1));
                    if (mode == 2) {
                        float u0 = v0 * g2v + b2v, u1 = v1 * g2v + b2v;
                        v0 = u0 > 0.f ? u0 : 0.f;
                        v1 = u1 > 0.f ? u1 : 0.f;
                    }
                }
                int n = bn0 + wn + (nt << 3) + 2 * tg;
                *(float2*)&C[(long long)m * N + n] = make_float2(v0, v1);
            }
        }
    }
}

// ---------------- host ----------------
extern "C" void kernel_launch(void* const* d_in, const int* in_sizes, int n_in,
                              void* d_out, int out_size) {
    const float* x     = (const float*)d_in[0];
    const float* w_gw  = (const float*)d_in[1];
    const float* gg    = (const float*)d_in[2];
    const float* bg    = (const float*)d_in[3];
    const float* w_fm  = (const float*)d_in[4];
    const float* gfm   = (const float*)d_in[5];
    const float* bfm   = (const float*)d_in[6];
    const float* w_cv2 = (const float*)d_in[7];
    const float* gcv   = (const float*)d_in[8];
    const float* bcv   = (const float*)d_in[9];
    const float* w_gf  = (const float*)d_in[10];
    const float* ggf   = (const float*)d_in[11];
    const float* bgf   = (const float*)d_in[12];
    const float* ggf2  = (const float*)d_in[13];
    const float* bgf2  = (const float*)d_in[14];
    const float* w_out = (const float*)d_in[15];
    float* out = (float*)d_out;

    float *p_spd, *p_w0, *p_pool, *p_X1, *p_cat, *p_mp, *p_weight, *p_f, *p_wd, *p_col, *p_tw;
    cudaGetSymbolAddress((void**)&p_spd,    g_spd);
    cudaGetSymbolAddress((void**)&p_w0,     g_w0);
    cudaGetSymbolAddress((void**)&p_pool,   g_pool);
    cudaGetSymbolAddress((void**)&p_X1,     g_X1);
    cudaGetSymbolAddress((void**)&p_cat,    g_cat);
    cudaGetSymbolAddress((void**)&p_mp,     g_mp);
    cudaGetSymbolAddress((void**)&p_weight, g_weight);
    cudaGetSymbolAddress((void**)&p_f,      g_f);
    cudaGetSymbolAddress((void**)&p_wd,     g_wd);
    cudaGetSymbolAddress((void**)&p_col,    g_col);
    cudaGetSymbolAddress((void**)&p_tw,     g_tw);

    init_tw_kernel<<<64, 256>>>();
    spd_kernel<<<131072, 256>>>(x);

    {
        dim3 g(128, 5, 8);
        hgemm_kernel<<<g, 256>>>(w_gw, p_spd, p_w0, 576, 16384, 256,
                                 0LL, 256LL * 16384, 576LL * 16384,
                                 gg, bg, nullptr, nullptr, 1);
    }
    avgpool_kernel<<<73728, 256>>>();

    {
        dim3 g(1, 288, 8);
        hgemm_kernel<<<g, 256>>>(p_pool, p_tw, p_X1, 36864, 128, 128,
                                 576LL * 16384, 0LL, 288LL * 16384,
                                 nullptr, nullptr, nullptr, nullptr, 0);
    }
    fft_col_kernel<<<2304, 256>>>();

    {
        dim3 g(32, 3, 8);
        hgemm_kernel<<<g, 256>>>(w_fm, p_cat, p_weight, 288, 4096, 1152,
                                 0LL, 1152LL * 4096, 576LL * 4096,
                                 gfm, bfm, nullptr, nullptr, 1);
    }
    maxpool_kernel<<<36864, 256>>>();

    {
        dim3 g(32, 3, 8);
        hgemm_kernel<<<g, 256>>>(w_cv2, p_mp, p_weight + 288 * 4096, 288, 4096, 288,
                                 0LL, 288LL * 4096, 576LL * 4096,
                                 gcv, bcv, nullptr, nullptr, 1);
    }
    im2col_kernel<<<294912, 256>>>();

    {
        dim3 g(32, 5, 8);
        hgemm_kernel<<<g, 256>>>(w_gf, p_col, p_f, 576, 4096, 2304,
                                 0LL, 2304LL * 4096, 576LL * 4096,
                                 ggf, bgf, ggf2, bgf2, 2);
    }
    softmax_wd_kernel<<<8192, 256>>>();

    {
        dim3 g(32, 1, 8);
        hgemm_kernel<<<g, 256>>>(w_out, p_wd, out, 128, 4096, 576,
                                 0LL, 576LL * 4096, 128LL * 4096,
                                 nullptr, nullptr, nullptr, nullptr, 0);
    }
}

// round 7
// speedup vs baseline: 2.3468x; 1.1978x over previous
#include <cuda_runtime.h>
#include <cuda_bf16.h>
#include <stdint.h>
#include <math.h>

#define THREADS 256
typedef unsigned short ushort_t;

// ---------------- fp32 intermediates ----------------
__device__ float g_spd[33554432];     // (8,256,128,128) fp32 (im2col gather source)
__device__ float g_w0[75497472];      // (8,576,128,128)
__device__ float g_pool2[37748736];   // (8,288,128,128) x2 half fp32 (maxpool source)
__device__ float g_X1[37748736];      // (8,288,128,128)
__device__ float g_weight[18874368];  // (8,576,64,64)
__device__ float g_f[18874368];       // (8,576,64,64)
__device__ float g_tw[16384];
__device__ float g_ct[128];
__device__ float g_st[128];

// ---------------- packed bf16 hi/lo (2 k's per uint32, low16 = even k) ----------------
__device__ uint32_t g_spdPh[16777216], g_spdPl[16777216];   // B: (8,128 k2,16384)
__device__ uint32_t g_poolAh[18874368], g_poolAl[18874368]; // A rows: (8*288*128, 64 words)
__device__ uint32_t g_catPh[18874368],  g_catPl[18874368];  // B: (8,576 k2,4096)
__device__ uint32_t g_mpPh[4718592],    g_mpPl[4718592];    // B: (8,144 k2,4096)
__device__ uint32_t g_colPh[37748736],  g_colPl[37748736];  // B: (8,1152 k2,4096)
__device__ uint32_t g_wdPh[9437184],    g_wdPl[9437184];    // B: (8,288 k2,4096)
__device__ uint32_t g_twBh[8192],       g_twBl[8192];       // B: (64 k2,128)
__device__ uint32_t g_wgwh[73728],  g_wgwl[73728];          // A 576x128w
__device__ uint32_t g_wfmh[165888], g_wfml[165888];         // A 288x576w
__device__ uint32_t g_wcvh[41472],  g_wcvl[41472];          // A 288x144w
__device__ uint32_t g_wgfh[663552], g_wgfl[663552];         // A 576x1152w
__device__ uint32_t g_wouth[36864], g_woutl[36864];         // A 128x288w

__device__ __forceinline__ void split2(float a, float b, uint32_t& hw, uint32_t& lw) {
    __nv_bfloat16 ah = __float2bfloat16(a), bh = __float2bfloat16(b);
    __nv_bfloat16 al = __float2bfloat16(a - __bfloat162float(ah));
    __nv_bfloat16 bl = __float2bfloat16(b - __bfloat162float(bh));
    hw = (uint32_t)*(ushort_t*)&ah | ((uint32_t)*(ushort_t*)&bh << 16);
    lw = (uint32_t)*(ushort_t*)&al | ((uint32_t)*(ushort_t*)&bl << 16);
}

__device__ __forceinline__ void stp(uint32_t* Wh, uint32_t* Wl, size_t wordIdx, int par, float v) {
    __nv_bfloat16 h = __float2bfloat16(v);
    __nv_bfloat16 l = __float2bfloat16(v - __bfloat162float(h));
    ((ushort_t*)Wh)[wordIdx * 2 + par] = *(ushort_t*)&h;
    ((ushort_t*)Wl)[wordIdx * 2 + par] = *(ushort_t*)&l;
}

__global__ void init_tw_kernel() {
    int i = blockIdx.x * blockDim.x + threadIdx.x;
    const double TWO_PI = 6.283185307179586476925286766559;
    if (i < 16384) {
        int q = i >> 7, v = i & 127;
        if (v < 64)
            g_tw[i] = (float)cos(TWO_PI * (double)((q * v) & 127) / 128.0);
        else
            g_tw[i] = (float)(-sin(TWO_PI * (double)((q * (v - 64)) & 127) / 128.0));
    }
    if (i < 128) {
        g_ct[i] = (float)cos(TWO_PI * (double)i / 128.0);
        g_st[i] = (float)sin(TWO_PI * (double)i / 128.0);
    }
}

__global__ void twpack_kernel() {
    int i = blockIdx.x * blockDim.x + threadIdx.x;
    if (i >= 8192) return;
    int k2 = i >> 7, v = i & 127;
    split2(g_tw[(2 * k2) * 128 + v], g_tw[(2 * k2 + 1) * 128 + v], g_twBh[i], g_twBl[i]);
}

__global__ void wsplit_kernel(const float* __restrict__ W, uint32_t* __restrict__ Wh,
                              uint32_t* __restrict__ Wl, int nwords) {
    int i = blockIdx.x * THREADS + threadIdx.x;
    if (i >= nwords) return;
    split2(W[2 * i], W[2 * i + 1], Wh[i], Wl[i]);
}

__global__ void spd_kernel(const float* __restrict__ x) {
    int i = blockIdx.x * THREADS + threadIdx.x;
    if (i >= 33554432) return;
    int q = i & 127, p = (i >> 7) & 127, s = (i >> 14) & 255, b = i >> 22;
    int quad = s >> 6, c = s & 63;
    int r  = 2 * p + (quad & 1);
    int cc = 2 * q + (quad >> 1);
    float v = x[((size_t)(b * 64 + c) * 256 + r) * 256 + cc];
    g_spd[i] = v;
    int n = i & 16383;
    stp(g_spdPh, g_spdPl, ((size_t)(b * 128 + (s >> 1)) << 14) + n, s & 1, v);
}

__global__ void avgpool_kernel() {
    int i = blockIdx.x * THREADS + threadIdx.x;
    if (i >= 18874368) return;
    int q4 = (i & 31) << 2;
    int p  = (i >> 5) & 127;
    int cb = i >> 12;
    int ch = cb % 576, b = cb / 576;
    float4 o = make_float4(0.f, 0.f, 0.f, 0.f);
    if (p < 127) {
        const float* s = g_w0 + ((size_t)cb << 14);
        int ofs = (p << 7) + q4;
        float4 a = *(const float4*)(s + ofs);
        float4 bb = *(const float4*)(s + ofs + 128);
        o.x = 0.25f * (a.x + a.y + bb.x + bb.y);
        o.y = 0.25f * (a.y + a.z + bb.y + bb.z);
        o.z = 0.25f * (a.z + a.w + bb.z + bb.w);
        if (q4 < 124) {
            float a4 = s[ofs + 4], b4 = s[ofs + 132];
            o.w = 0.25f * (a.w + a4 + bb.w + b4);
        }
    }
    if (ch < 288) {
        uint32_t h0, l0, h1, l1;
        split2(o.x, o.y, h0, l0);
        split2(o.z, o.w, h1, l1);
        size_t wb = ((size_t)(b * 288 + ch) << 13) + (p << 6) + (q4 >> 1);
        g_poolAh[wb] = h0; g_poolAh[wb + 1] = h1;
        g_poolAl[wb] = l0; g_poolAl[wb + 1] = l1;
    } else {
        *(float4*)(g_pool2 + ((size_t)(b * 288 + ch - 288) << 14) + (p << 7) + q4) = o;
    }
}

__global__ void maxpool_kernel() {
    int i = blockIdx.x * THREADS + threadIdx.x;
    if (i >= 9437184) return;
    int v = i & 63, u = (i >> 6) & 63;
    int cb = i >> 12;
    int c = cb % 288, b = cb / 288;
    const float* s = g_pool2 + ((size_t)(b * 288 + c) << 14);
    int r0 = max(2 * u - 1, 0), r1 = min(2 * u + 1, 126);
    int c0 = max(2 * v - 1, 0), c1 = min(2 * v + 1, 126);
    float m = -3.4e38f;
    for (int r = r0; r <= r1; r++)
        for (int cc = c0; cc <= c1; cc++)
            m = fmaxf(m, s[(r << 7) + cc]);
    stp(g_mpPh, g_mpPl, ((size_t)(b * 144 + (c >> 1)) << 12) + (i & 4095), c & 1, m);
}

__global__ void im2col_kernel() {
    int i = blockIdx.x * THREADS + threadIdx.x;
    if (i >= 75497472) return;
    int n = i & 4095;
    int v = n & 63, u = n >> 6;
    int kb = i >> 12;
    int k = kb % 2304, b = kb / 2304;
    int ic = k / 9, t = k - ic * 9;
    int di = t / 3, dj = t - di * 3;
    int r  = 2 * u + di - 1;
    int cc = 2 * v + dj - 1;
    float val = 0.f;
    if ((unsigned)r < 128u && (unsigned)cc < 128u)
        val = g_spd[((size_t)(b * 256 + ic) << 14) + (r << 7) + cc];
    stp(g_colPh, g_colPl, ((size_t)(b * 1152 + (k >> 1)) << 12) + n, k & 1, val);
}

__global__ __launch_bounds__(256) void fft_col_kernel() {
    __shared__ float Xre[128][32];
    __shared__ float Xim[128][32];
    __shared__ float cs[128], sn[128];
    int blk = blockIdx.x;
    int b = blk / 288, c = blk % 288;
    int tid = threadIdx.x;
    if (tid < 128) { cs[tid] = g_ct[tid]; sn[tid] = g_st[tid]; }
    const float* X1 = g_X1 + (size_t)(b * 288 + c) * 16384;
    int par = c & 1;
    size_t wLRe = ((size_t)(b * 576) + (c >> 1)) << 12;
    size_t wLIm = wLRe + ((size_t)144 << 12);
    size_t wHRe = wLRe + ((size_t)288 << 12);
    size_t wHIm = wLRe + ((size_t)432 << 12);
    for (int half = 0; half < 2; half++) {
        int v0 = half << 5;
        __syncthreads();
        for (int e = tid; e < 4096; e += 256) {
            int p = e >> 5, v = e & 31;
            Xre[p][v] = X1[(p << 7) + v0 + v];
            Xim[p][v] = X1[(p << 7) + 64 + v0 + v];
        }
        __syncthreads();
        for (int r = 0; r < 4; r++) {
            int item = (r << 8) + tid;
            int u = item >> 5, v = item & 31;
            float r0 = 0.f, i0 = 0.f, r1 = 0.f, i1 = 0.f;
            float r2 = 0.f, i2 = 0.f, r3 = 0.f, i3 = 0.f;
            int u1 = u, u2 = (2 * u) & 127, u3 = (3 * u) & 127, u4 = (4 * u) & 127;
            int idx = 0;
            #pragma unroll 4
            for (int p = 0; p < 128; p += 4) {
                {
                    float cc = cs[idx], ss = sn[idx];
                    float xr = Xre[p][v], xi = Xim[p][v];
                    r0 = fmaf(xr, cc, r0); r0 = fmaf(xi, ss, r0);
                    i0 = fmaf(xi, cc, i0); i0 = fmaf(-xr, ss, i0);
                }
                {
                    int id = (idx + u1) & 127;
                    float cc = cs[id], ss = sn[id];
                    float xr = Xre[p + 1][v], xi = Xim[p + 1][v];
                    r1 = fmaf(xr, cc, r1); r1 = fmaf(xi, ss, r1);
                    i1 = fmaf(xi, cc, i1); i1 = fmaf(-xr, ss, i1);
                }
                {
                    int id = (idx + u2) & 127;
                    float cc = cs[id], ss = sn[id];
                    float xr = Xre[p + 2][v], xi = Xim[p + 2][v];
                    r2 = fmaf(xr, cc, r2); r2 = fmaf(xi, ss, r2);
                    i2 = fmaf(xi, cc, i2); i2 = fmaf(-xr, ss, i2);
                }
                {
                    int id = (idx + u3) & 127;
                    float cc = cs[id], ss = sn[id];
                    float xr = Xre[p + 3][v], xi = Xim[p + 3][v];
                    r3 = fmaf(xr, cc, r3); r3 = fmaf(xi, ss, r3);
                    i3 = fmaf(xi, cc, i3); i3 = fmaf(-xr, ss, i3);
                }
                idx = (idx + u4) & 127;
            }
            float rA = r0 + r2, iA = i0 + i2;
            float rB = r0 - r2, iB = i0 - i2;
            float rC = r1 + r3, iC = i1 + i3;
            float rD = r1 - r3, iD = i1 - i3;
            int vv = v0 + v;
            int off_u   = (u << 6) + vv;
            int off_u32 = ((u + 32) << 6) + vv;
            stp(g_catPh, g_catPl, wLRe + off_u,   par, rA + rC);
            stp(g_catPh, g_catPl, wLIm + off_u,   par, iA + iC);
            stp(g_catPh, g_catPl, wLRe + off_u32, par, rB + iD);
            stp(g_catPh, g_catPl, wLIm + off_u32, par, iB - rD);
            stp(g_catPh, g_catPl, wHRe + off_u,   par, rA - rC);
            stp(g_catPh, g_catPl, wHIm + off_u,   par, iA - iC);
            stp(g_catPh, g_catPl, wHRe + off_u32, par, rB - iD);
            stp(g_catPh, g_catPl, wHIm + off_u32, par, iB + rD);
        }
    }
}

__global__ void softmax_wd_kernel() {
    int i = blockIdx.x * THREADS + threadIdx.x;
    if (i >= 2097152) return;
    int n = i & 4095;
    int cb = i >> 12;
    int c = cb & 63, b = cb >> 6;
    size_t base = (size_t)(b * 576 + c * 9) * 4096 + n;
    float w[9];
    float mx = -3.4e38f;
    #pragma unroll
    for (int t = 0; t < 9; t++) { w[t] = g_weight[base + t * 4096]; mx = fmaxf(mx, w[t]); }
    float sum = 0.f;
    #pragma unroll
    for (int t = 0; t < 9; t++) { w[t] = expf(w[t] - mx); sum += w[t]; }
    float inv = 1.f / sum;
    #pragma unroll
    for (int t = 0; t < 9; t++) {
        float v = g_f[base + t * 4096] * w[t] * inv;
        int k = c * 9 + t;
        stp(g_wdPh, g_wdPl, ((size_t)(b * 288 + (k >> 1)) << 12) + n, k & 1, v);
    }
}

// ---------------- tensor-core GEMM on pre-split packed bf16, cp.async pipeline ----------------
#define MMA_BF16(d, a, b0_, b1_) \
    asm volatile("mma.sync.aligned.m16n8k16.row.col.f32.bf16.bf16.f32 " \
        "{%0,%1,%2,%3},{%4,%5,%6,%7},{%8,%9},{%0,%1,%2,%3};" \
        : "+f"(d[0]), "+f"(d[1]), "+f"(d[2]), "+f"(d[3]) \
        : "r"(a[0]), "r"(a[1]), "r"(a[2]), "r"(a[3]), "r"(b0_), "r"(b1_))

#define CPA(dst, src, sz) asm volatile("cp.async.cg.shared.global [%0], [%1], 16, %2;" \
        :: "r"(dst), "l"(src), "r"(sz))
#define CPC() asm volatile("cp.async.commit_group;")
#define CPW(n) asm volatile("cp.async.wait_group %0;" :: "n"(n))

__device__ __forceinline__ uint32_t smaddr(const void* p) {
    return (uint32_t)__cvta_generic_to_shared(p);
}

// A smem row stride = 12 words (48B -> 16B-aligned cp.async dsts, conflict-free frag loads)
__global__ __launch_bounds__(256) void bgemm_kernel(
    const uint32_t* __restrict__ Ah, const uint32_t* __restrict__ Al,
    const uint32_t* __restrict__ Bh, const uint32_t* __restrict__ Bl,
    float* __restrict__ C, int M, int N, int K,
    long long sA, long long sB, long long sC,
    const float* __restrict__ G1, const float* __restrict__ Bi1,
    const float* __restrict__ G2, const float* __restrict__ Bi2, int mode)
{
    __shared__ uint32_t sAh[2][1536], sAl[2][1536];
    __shared__ uint32_t sBh[2][1088], sBl[2][1088];    // 8 k2-rows * 136
    int tid = threadIdx.x;
    int bn0 = blockIdx.x << 7, bm0 = blockIdx.y << 7;
    int Kw = K >> 1;
    Ah += (long long)blockIdx.z * sA;  Al += (long long)blockIdx.z * sA;
    Bh += (long long)blockIdx.z * sB;  Bl += (long long)blockIdx.z * sB;
    C  += (long long)blockIdx.z * sC;

    int aRow = tid >> 1, wofs = (tid & 1) << 2;
    bool aOk = (bm0 + aRow) < M;
    uint32_t szA = aOk ? 16u : 0u;
    const uint32_t* ApH = Ah + (long long)(aOk ? (bm0 + aRow) : 0) * Kw + wofs;
    const uint32_t* ApL = Al + (long long)(aOk ? (bm0 + aRow) : 0) * Kw + wofs;
    int bK2 = tid >> 5, bN0 = (tid & 31) << 2;
    const uint32_t* BpH = Bh + (long long)bK2 * N + bn0 + bN0;
    const uint32_t* BpL = Bl + (long long)bK2 * N + bn0 + bN0;

    uint32_t dAh[2], dAl[2], dBh[2], dBl[2];
    dAh[0] = smaddr(&sAh[0][aRow * 12 + wofs]); dAh[1] = smaddr(&sAh[1][aRow * 12 + wofs]);
    dAl[0] = smaddr(&sAl[0][aRow * 12 + wofs]); dAl[1] = smaddr(&sAl[1][aRow * 12 + wofs]);
    dBh[0] = smaddr(&sBh[0][bK2 * 136 + bN0]);  dBh[1] = smaddr(&sBh[1][bK2 * 136 + bN0]);
    dBl[0] = smaddr(&sBl[0][bK2 * 136 + bN0]);  dBl[1] = smaddr(&sBl[1][bK2 * 136 + bN0]);

    int wid = tid >> 5, lane = tid & 31;
    int wm = (wid >> 2) << 6, wn = (wid & 3) << 5;
    int g = lane >> 2, tg = lane & 3;

    float acc[4][4][4];
    #pragma unroll
    for (int i = 0; i < 4; i++)
        #pragma unroll
        for (int j = 0; j < 4; j++)
            #pragma unroll
            for (int r = 0; r < 4; r++) acc[i][j][r] = 0.f;

    int nstage = K >> 4;

    CPA(dAh[0], ApH, szA); CPA(dAl[0], ApL, szA);
    CPA(dBh[0], BpH, 16);  CPA(dBl[0], BpL, 16);
    CPC();

    int buf = 0;
    for (int s = 0; s < nstage; s++) {
        bool hasNext = (s + 1) < nstage;
        if (hasNext) {
            long long kw = (long long)(s + 1) << 3;
            CPA(dAh[buf ^ 1], ApH + kw, szA);
            CPA(dAl[buf ^ 1], ApL + kw, szA);
            CPA(dBh[buf ^ 1], BpH + kw * N, 16);
            CPA(dBl[buf ^ 1], BpL + kw * N, 16);
            CPC();
            CPW(1);
        } else {
            CPW(0);
        }
        __syncthreads();

        uint32_t ah[4][4], al[4][4];
        #pragma unroll
        for (int mt = 0; mt < 4; mt++) {
            int r0 = (wm + (mt << 4) + g) * 12, r8 = r0 + 96;
            ah[mt][0] = sAh[buf][r0 + tg];     ah[mt][1] = sAh[buf][r8 + tg];
            ah[mt][2] = sAh[buf][r0 + tg + 4]; ah[mt][3] = sAh[buf][r8 + tg + 4];
            al[mt][0] = sAl[buf][r0 + tg];     al[mt][1] = sAl[buf][r8 + tg];
            al[mt][2] = sAl[buf][r0 + tg + 4]; al[mt][3] = sAl[buf][r8 + tg + 4];
        }
        #pragma unroll
        for (int nt = 0; nt < 4; nt++) {
            int nid = wn + (nt << 3) + g;
            uint32_t bh0 = sBh[buf][tg * 136 + nid];
            uint32_t bh1 = sBh[buf][(tg + 4) * 136 + nid];
            uint32_t bl0 = sBl[buf][tg * 136 + nid];
            uint32_t bl1 = sBl[buf][(tg + 4) * 136 + nid];
            #pragma unroll
            for (int mt = 0; mt < 4; mt++) {
                MMA_BF16(acc[mt][nt], ah[mt], bh0, bh1);
                MMA_BF16(acc[mt][nt], ah[mt], bl0, bl1);
                MMA_BF16(acc[mt][nt], al[mt], bh0, bh1);
            }
        }
        __syncthreads();
        buf ^= 1;
    }

    #pragma unroll
    for (int mt = 0; mt < 4; mt++) {
        int mbase = bm0 + wm + (mt << 4) + g;
        #pragma unroll
        for (int half = 0; half < 2; half++) {
            int m = mbase + half * 8;
            if (m >= M) continue;
            float g1v = 0.f, b1v = 0.f, g2v = 0.f, b2v = 0.f;
            if (mode >= 1) { g1v = G1[m]; b1v = Bi1[m]; }
            if (mode == 2) { g2v = G2[m]; b2v = Bi2[m]; }
            #pragma unroll
            for (int nt = 0; nt < 4; nt++) {
                float v0 = acc[mt][nt][half * 2 + 0];
                float v1 = acc[mt][nt][half * 2 + 1];
                if (mode >= 1) {
                    float t0 = v0 * g1v + b1v;
                    float t1 = v1 * g1v + b1v;
                    v0 = t0 / (1.f + expf(-t0));
                    v1 = t1 / (1.f + expf(-t1));
                    if (mode == 2) {
                        float u0 = v0 * g2v + b2v, u1 = v1 * g2v + b2v;
                        v0 = u0 > 0.f ? u0 : 0.f;
                        v1 = u1 > 0.f ? u1 : 0.f;
                    }
                }
                int n = bn0 + wn + (nt << 3) + 2 * tg;
                *(float2*)&C[(long long)m * N + n] = make_float2(v0, v1);
            }
        }
    }
}

// ---------------- host ----------------
extern "C" void kernel_launch(void* const* d_in, const int* in_sizes, int n_in,
                              void* d_out, int out_size) {
    const float* x     = (const float*)d_in[0];
    const float* w_gw  = (const float*)d_in[1];
    const float* gg    = (const float*)d_in[2];
    const float* bg    = (const float*)d_in[3];
    const float* w_fm  = (const float*)d_in[4];
    const float* gfm   = (const float*)d_in[5];
    const float* bfm   = (const float*)d_in[6];
    const float* w_cv2 = (const float*)d_in[7];
    const float* gcv   = (const float*)d_in[8];
    const float* bcv   = (const float*)d_in[9];
    const float* w_gf  = (const float*)d_in[10];
    const float* ggf   = (const float*)d_in[11];
    const float* bgf   = (const float*)d_in[12];
    const float* ggf2  = (const float*)d_in[13];
    const float* bgf2  = (const float*)d_in[14];
    const float* w_out = (const float*)d_in[15];
    float* out = (float*)d_out;

    float *p_w0, *p_X1, *p_weight, *p_f;
    uint32_t *p_spdPh, *p_spdPl, *p_poolAh, *p_poolAl, *p_catPh, *p_catPl;
    uint32_t *p_mpPh, *p_mpPl, *p_colPh, *p_colPl, *p_wdPh, *p_wdPl, *p_twBh, *p_twBl;
    uint32_t *p_wgwh, *p_wgwl, *p_wfmh, *p_wfml, *p_wcvh, *p_wcvl, *p_wgfh, *p_wgfl, *p_wouth, *p_woutl;
    cudaGetSymbolAddress((void**)&p_w0,     g_w0);
    cudaGetSymbolAddress((void**)&p_X1,     g_X1);
    cudaGetSymbolAddress((void**)&p_weight, g_weight);
    cudaGetSymbolAddress((void**)&p_f,      g_f);
    cudaGetSymbolAddress((void**)&p_spdPh,  g_spdPh);  cudaGetSymbolAddress((void**)&p_spdPl,  g_spdPl);
    cudaGetSymbolAddress((void**)&p_poolAh, g_poolAh); cudaGetSymbolAddress((void**)&p_poolAl, g_poolAl);
    cudaGetSymbolAddress((void**)&p_catPh,  g_catPh);  cudaGetSymbolAddress((void**)&p_catPl,  g_catPl);
    cudaGetSymbolAddress((void**)&p_mpPh,   g_mpPh);   cudaGetSymbolAddress((void**)&p_mpPl,   g_mpPl);
    cudaGetSymbolAddress((void**)&p_colPh,  g_colPh);  cudaGetSymbolAddress((void**)&p_colPl,  g_colPl);
    cudaGetSymbolAddress((void**)&p_wdPh,   g_wdPh);   cudaGetSymbolAddress((void**)&p_wdPl,   g_wdPl);
    cudaGetSymbolAddress((void**)&p_twBh,   g_twBh);   cudaGetSymbolAddress((void**)&p_twBl,   g_twBl);
    cudaGetSymbolAddress((void**)&p_wgwh,   g_wgwh);   cudaGetSymbolAddress((void**)&p_wgwl,   g_wgwl);
    cudaGetSymbolAddress((void**)&p_wfmh,   g_wfmh);   cudaGetSymbolAddress((void**)&p_wfml,   g_wfml);
    cudaGetSymbolAddress((void**)&p_wcvh,   g_wcvh);   cudaGetSymbolAddress((void**)&p_wcvl,   g_wcvl);
    cudaGetSymbolAddress((void**)&p_wgfh,   g_wgfh);   cudaGetSymbolAddress((void**)&p_wgfl,   g_wgfl);
    cudaGetSymbolAddress((void**)&p_wouth,  g_wouth);  cudaGetSymbolAddress((void**)&p_woutl,  g_woutl);

    init_tw_kernel<<<64, 256>>>();
    twpack_kernel<<<32, 256>>>();
    wsplit_kernel<<<288, 256>>>(w_gw, p_wgwh, p_wgwl, 73728);
    wsplit_kernel<<<648, 256>>>(w_fm, p_wfmh, p_wfml, 165888);
    wsplit_kernel<<<162, 256>>>(w_cv2, p_wcvh, p_wcvl, 41472);
    wsplit_kernel<<<2592, 256>>>(w_gf, p_wgfh, p_wgfl, 663552);
    wsplit_kernel<<<144, 256>>>(w_out, p_wouth, p_woutl, 36864);
    spd_kernel<<<131072, 256>>>(x);

    {
        dim3 g(128, 5, 8);
        bgemm_kernel<<<g, 256>>>(p_wgwh, p_wgwl, p_spdPh, p_spdPl, p_w0,
                                 576, 16384, 256, 0LL, 2097152LL, 9437184LL,
                                 gg, bg, nullptr, nullptr, 1);
    }
    avgpool_kernel<<<73728, 256>>>();

    {
        dim3 g(1, 288, 8);
        bgemm_kernel<<<g, 256>>>(p_poolAh, p_poolAl, p_twBh, p_twBl, p_X1,
                                 36864, 128, 128, 2359296LL, 0LL, 4718592LL,
                                 nullptr, nullptr, nullptr, nullptr, 0);
    }
    fft_col_kernel<<<2304, 256>>>();

    {
        dim3 g(32, 3, 8);
        bgemm_kernel<<<g, 256>>>(p_wfmh, p_wfml, p_catPh, p_catPl, p_weight,
                                 288, 4096, 1152, 0LL, 2359296LL, 2359296LL,
                                 gfm, bfm, nullptr, nullptr, 1);
    }
    maxpool_kernel<<<36864, 256>>>();

    {
        dim3 g(32, 3, 8);
        bgemm_kernel<<<g, 256>>>(p_wcvh, p_wcvl, p_mpPh, p_mpPl, p_weight + 288 * 4096,
                                 288, 4096, 288, 0LL, 589824LL, 2359296LL,
                                 gcv, bcv, nullptr, nullptr, 1);
    }
    im2col_kernel<<<294912, 256>>>();

    {
        dim3 g(32, 5, 8);
        bgemm_kernel<<<g, 256>>>(p_wgfh, p_wgfl, p_colPh, p_colPl, p_f,
                                 576, 4096, 2304, 0LL, 4718592LL, 2359296LL,
                                 ggf, bgf, ggf2, bgf2, 2);
    }
    softmax_wd_kernel<<<8192, 256>>>();

    {
        dim3 g(32, 1, 8);
        bgemm_kernel<<<g, 256>>>(p_wouth, p_woutl, p_wdPh, p_wdPl, out,
                                 128, 4096, 576, 0LL, 1179648LL, 524288LL,
                                 nullptr, nullptr, nullptr, nullptr, 0);
    }
}